// round 4
// baseline (speedup 1.0000x reference)
#include <cuda_runtime.h>
#include <cstdint>

#define LLEN 1024
#define NBH 16

typedef unsigned long long ull;

// Fallbacks in case d_out only holds V (defensive vs. output-layout surprises).
__device__ float g_att_fb[(size_t)NBH * LLEN * LLEN];
__device__ float g_ent_fb[(size_t)NBH * LLEN];

// ---- packed f32x2 helpers (FFMA2: 2 MACs per FMA-pipe issue) ----
__device__ __forceinline__ ull pack2(float lo, float hi) {
    ull r; asm("mov.b64 %0, {%1, %2};" : "=l"(r) : "f"(lo), "f"(hi)); return r;
}
__device__ __forceinline__ ull dup2(float x) {
    ull r; asm("mov.b64 %0, {%1, %1};" : "=l"(r) : "f"(x)); return r;
}
__device__ __forceinline__ ull ffma2(ull a, ull b, ull c) {
    ull d; asm("fma.rn.f32x2 %0, %1, %2, %3;" : "=l"(d) : "l"(a), "l"(b), "l"(c)); return d;
}
__device__ __forceinline__ float2 unpk2(ull v) {
    float2 f; asm("mov.b64 {%0, %1}, %2;" : "=f"(f.x), "=f"(f.y) : "l"(v)); return f;
}
// MUFU.TANH (sm_75+)
__device__ __forceinline__ float tanha(float x) {
    float y; asm("tanh.approx.f32 %0, %1;" : "=f"(y) : "f"(x)); return y;
}

// ============================================================================
// Fused kernel A (unchanged from R2): pair-tile scores + elementwise att.
// ============================================================================
__global__ __launch_bounds__(128) void kA(const float* __restrict__ q,
                                          const float* __restrict__ kk,
                                          float* __restrict__ att,
                                          const float* __restrict__ p0,
                                          const float* __restrict__ p1,
                                          const float* __restrict__ p2,
                                          const float* __restrict__ p3) {
    __shared__ float sb_[8704];   // phase1: 4x[32][68]; phase2: 2x[64][68]
    const int p = blockIdx.x, bh = blockIdx.y;
    const int b = bh >> 3, h = bh & 7;
    int i = (int)((__fsqrt_rn(8.0f * p + 1.0f) - 1.0f) * 0.5f);
    while ((i + 1) * (i + 2) / 2 <= p) i++;
    while (i * (i + 1) / 2 > p) i--;
    const int j = p - i * (i + 1) / 2;

    const int tid = threadIdx.x;
    const int half = tid >> 6, t6 = tid & 63;
    const int l0 = (t6 >> 3) << 3, s0 = (t6 & 7) << 3;

    float* Qi = sb_;            // [32][68] each, k-major [e][row]
    float* Kj = sb_ + 2176;
    float* Qj = sb_ + 4352;
    float* Ki = sb_ + 6528;
    const float* A_ = half ? Qj : Qi;
    const float* B_ = half ? Ki : Kj;

    ull acc[8][4];
    #pragma unroll
    for (int r = 0; r < 8; r++)
        #pragma unroll
        for (int c = 0; c < 4; c++) acc[r][c] = 0ull;

    for (int c = 0; c < 2; c++) {
        __syncthreads();
        const int e0c = c << 5;
        #pragma unroll
        for (int t = tid; t < 2048; t += 128) {
            int tile = t >> 9, r = (t >> 3) & 63, e4 = (t & 7) << 2;
            int row; const float* src; float* dst;
            if (tile == 0)      { row = i * 64 + r; src = q;  dst = Qi; }
            else if (tile == 1) { row = j * 64 + r; src = kk; dst = Kj; }
            else if (tile == 2) { row = j * 64 + r; src = q;  dst = Qj; }
            else                { row = i * 64 + r; src = kk; dst = Ki; }
            float4 v = *(const float4*)(src + (((size_t)(b * LLEN + row)) * 8 + h) * 64 + e0c + e4);
            dst[(e4 + 0) * 68 + r] = v.x; dst[(e4 + 1) * 68 + r] = v.y;
            dst[(e4 + 2) * 68 + r] = v.z; dst[(e4 + 3) * 68 + r] = v.w;
        }
        __syncthreads();
        #pragma unroll 8
        for (int e = 0; e < 32; e++) {
            float4 a0 = *(const float4*)(A_ + e * 68 + l0);
            float4 a1 = *(const float4*)(A_ + e * 68 + l0 + 4);
            float4 b0 = *(const float4*)(B_ + e * 68 + s0);
            float4 b1 = *(const float4*)(B_ + e * 68 + s0 + 4);
            ull bp[4] = {pack2(b0.x, b0.y), pack2(b0.z, b0.w),
                         pack2(b1.x, b1.y), pack2(b1.z, b1.w)};
            float av[8] = {a0.x, a0.y, a0.z, a0.w, a1.x, a1.y, a1.z, a1.w};
            #pragma unroll
            for (int r = 0; r < 8; r++) {
                ull ad = dup2(av[r]);
                #pragma unroll
                for (int cc = 0; cc < 4; cc++) acc[r][cc] = ffma2(ad, bp[cc], acc[r][cc]);
            }
        }
    }

    __syncthreads();
    float* C1 = sb_;            // [64][68]
    float* C2 = sb_ + 4352;
    float* Cm = half ? C2 : C1;
    #pragma unroll
    for (int r = 0; r < 8; r++) {
        float o[8];
        #pragma unroll
        for (int cc = 0; cc < 4; cc++) {
            float2 f = unpk2(acc[r][cc]);
            o[2 * cc] = f.x * 0.125f; o[2 * cc + 1] = f.y * 0.125f;
        }
        float* pd = Cm + (l0 + r) * 68 + s0;
        *(float4*)pd       = make_float4(o[0], o[1], o[2], o[3]);
        *(float4*)(pd + 4) = make_float4(o[4], o[5], o[6], o[7]);
    }
    __syncthreads();

    const float gg = fminf(fmaxf(__expf(*p0), 1e-3f), 20.0f);
    const float tg = fminf(fmaxf(__expf(*p1), 1e-3f), 10.0f);
    const float gd = fminf(fmaxf(__expf(*p2), 1e-3f), 20.0f);
    const float td = fminf(fmaxf(__expf(*p3), 1e-3f), 10.0f);
    const float itg = 1.0f / tg, itd = 1.0f / td, gdd = gd / td;

    if (!(half && i == j)) {
        const int r = t6;
        const float* Cown = half ? C2 : C1;
        const float* Coth = half ? C1 : C2;
        const int lg  = (half ? j : i) * 64 + r;
        const int sg0 = (half ? i : j) * 64;
        float* arow = att + ((size_t)bh * LLEN + lg) * LLEN + sg0;
        const bool dg = (i == j);
        #pragma unroll
        for (int s4 = 0; s4 < 64; s4 += 4) {
            float4 g1 = *(const float4*)(Cown + r * 68 + s4);
            float o[4];
            #pragma unroll
            for (int v = 0; v < 4; v++) {
                float g1v = (&g1.x)[v];
                float g2v = Coth[(s4 + v) * 68 + r];
                float Ss = 0.5f * (g1v + g2v);
                float Aa = 0.5f * (g1v - g2v);
                float t1 = tanha(Ss * itg);
                float t2 = tanha(Aa * itd);
                float s1 = fmaf(tanha(0.5f * gg * t1), 0.5f, 0.5f);
                float s2 = fmaf(tanha(0.5f * gd * t2), 0.5f, 0.5f);
                float m = s1 * s2;
                if (dg && (s4 + v) == r) m = 0.0f;
                o[v] = fmaxf(tanha(Aa * gdd), 0.0f) * m;
            }
            *(float4*)(arow + s4) = make_float4(o[0], o[1], o[2], o[3]);
        }
    }
}

// ============================================================================
// K3 v2: occupancy fix. Tile 64 l-rows x 64 e-cols, 256 threads (8 warps),
// grid (16 l-tiles, 16 bh) = 256 blocks (~14 warps/SM vs 4 before).
// Micro 2x8 per thread, s streamed in 32-chunks, entropy via 4-thread stripes
// + shfl(width=4) reduce.
// ============================================================================
__global__ __launch_bounds__(256) void k3_av(const float* __restrict__ att,
                                             const float* __restrict__ val,
                                             float* __restrict__ vout,
                                             float* __restrict__ ent) {
    __shared__ float As[64][36];
    __shared__ float Vs[32][68];
    const int bh = blockIdx.y, b = bh >> 3, h = bh & 7;
    const int lb = blockIdx.x << 6;
    const int tid = threadIdx.x;
    const int eg = tid & 7, rg = tid >> 3;        // rg 0..31
    const int row0 = rg << 1, e0 = eg << 3;       // 2 rows, 8 cols per thread

    ull acc[2][4];
    #pragma unroll
    for (int r = 0; r < 2; r++)
        #pragma unroll
        for (int c = 0; c < 4; c++) acc[r][c] = 0ull;
    float entacc = 0.0f;

    const int erow = tid >> 2;          // entropy row 0..63
    const int esc  = (tid & 3) << 3;    // stripe offset within 32-chunk

    const float* attbase = att + ((size_t)bh * LLEN + lb) * LLEN;

    for (int cb = 0; cb < 32; cb++) {
        const int sb = cb << 5;
        __syncthreads();
        // As: 64 rows x 32 cols = 512 float4, 2 per thread
        #pragma unroll
        for (int t = tid; t < 512; t += 256) {
            int rr = t >> 3, c4 = (t & 7) << 2;
            *(float4*)&As[rr][c4] = *(const float4*)(attbase + (size_t)rr * LLEN + sb + c4);
        }
        // Vs: 32 rows x 64 cols = 512 float4, 2 per thread
        #pragma unroll
        for (int t = tid; t < 512; t += 256) {
            int rr = t >> 4, c4 = (t & 15) << 2;
            *(float4*)&Vs[rr][c4] = *(const float4*)(val + (((size_t)(b * LLEN + sb + rr)) * 8 + h) * 64 + c4);
        }
        __syncthreads();

        #pragma unroll
        for (int s4 = 0; s4 < 32; s4 += 4) {
            float4 a0 = *(const float4*)&As[row0][s4];
            float4 a1 = *(const float4*)&As[row0 + 1][s4];
            #pragma unroll
            for (int u = 0; u < 4; u++) {
                int ss = s4 + u;
                float4 w0 = *(const float4*)&Vs[ss][e0];
                float4 w1 = *(const float4*)&Vs[ss][e0 + 4];
                ull v2[4] = {pack2(w0.x, w0.y), pack2(w0.z, w0.w),
                             pack2(w1.x, w1.y), pack2(w1.z, w1.w)};
                ull ad0 = dup2((&a0.x)[u]);
                ull ad1 = dup2((&a1.x)[u]);
                #pragma unroll
                for (int c = 0; c < 4; c++) {
                    acc[0][c] = ffma2(ad0, v2[c], acc[0][c]);
                    acc[1][c] = ffma2(ad1, v2[c], acc[1][c]);
                }
            }
        }
        // entropy stripe: 4 threads per row, 8 cols each
        {
            float4 a = *(const float4*)&As[erow][esc];
            float4 c = *(const float4*)&As[erow][esc + 4];
            entacc += a.x * __logf(fmaxf(a.x, 1e-8f));
            entacc += a.y * __logf(fmaxf(a.y, 1e-8f));
            entacc += a.z * __logf(fmaxf(a.z, 1e-8f));
            entacc += a.w * __logf(fmaxf(a.w, 1e-8f));
            entacc += c.x * __logf(fmaxf(c.x, 1e-8f));
            entacc += c.y * __logf(fmaxf(c.y, 1e-8f));
            entacc += c.z * __logf(fmaxf(c.z, 1e-8f));
            entacc += c.w * __logf(fmaxf(c.w, 1e-8f));
        }
    }

    // entropy reduce across the 4 stripe threads (consecutive lanes)
    entacc += __shfl_down_sync(0xffffffffu, entacc, 1, 4);
    entacc += __shfl_down_sync(0xffffffffu, entacc, 2, 4);
    if ((tid & 3) == 0) ent[(size_t)bh * LLEN + lb + erow] = -entacc;

    #pragma unroll
    for (int r = 0; r < 2; r++) {
        int l = lb + row0 + r;
        float o[8];
        #pragma unroll
        for (int c = 0; c < 4; c++) {
            float2 f = unpk2(acc[r][c]);
            o[2 * c] = f.x; o[2 * c + 1] = f.y;
        }
        float* pd = vout + (((size_t)(b * LLEN + l)) * 8 + h) * 64 + e0;
        *(float4*)pd       = make_float4(o[0], o[1], o[2], o[3]);
        *(float4*)(pd + 4) = make_float4(o[4], o[5], o[6], o[7]);
    }
}

// ============================================================================
// Launch: kA -> k3. Graph-capturable, no alloc.
// ============================================================================
extern "C" void kernel_launch(void* const* d_in, const int* in_sizes, int n_in,
                              void* d_out, int out_size) {
    const float* q = (const float*)d_in[0];
    const float* k = (const float*)d_in[1];
    const float* v = (const float*)d_in[2];
    const float* lgg = (const float*)d_in[n_in - 4];
    const float* ltg = (const float*)d_in[n_in - 3];
    const float* lgd = (const float*)d_in[n_in - 2];
    const float* ltd = (const float*)d_in[n_in - 1];

    const long V_ELEMS   = (long)2 * LLEN * 8 * 64;
    const long ATT_ELEMS = (long)NBH * LLEN * LLEN;
    const long ENT_ELEMS = (long)NBH * LLEN;

    float* out = (float*)d_out;
    float* vptr = out;
    float* attp;
    float* entp;
    if ((long)out_size >= V_ELEMS + ATT_ELEMS + ENT_ELEMS) {
        attp = out + V_ELEMS;
        entp = out + V_ELEMS + ATT_ELEMS;
    } else {
        void* p1 = nullptr; void* p2 = nullptr;
        cudaGetSymbolAddress(&p1, g_att_fb);
        cudaGetSymbolAddress(&p2, g_ent_fb);
        attp = (float*)p1;
        entp = (float*)p2;
    }

    kA<<<dim3(136, 16), 128>>>(q, k, attp, lgg, ltg, lgd, ltd);
    k3_av<<<dim3(16, 16), 256>>>(attp, v, vptr, entp);
}

// round 7
// speedup vs baseline: 1.4926x; 1.4926x over previous
#include <cuda_runtime.h>
#include <cstdint>

#define LLEN 1024
#define NBH 16
#define NSPLIT 4
#define V_ELEMS_C 1048576
#define ENT_ELEMS_C 16384

typedef unsigned long long ull;

// Fallbacks in case d_out only holds V (defensive vs. output-layout surprises).
__device__ float g_att_fb[(size_t)NBH * LLEN * LLEN];
__device__ float g_ent_fb[(size_t)NBH * LLEN];
// Split-K partials (deterministic two-pass reduction; atomics would break
// the harness determinism requirement).
__device__ float g_pv[(size_t)NSPLIT * V_ELEMS_C];
__device__ float g_pe[(size_t)NSPLIT * ENT_ELEMS_C];

// ---- packed f32x2 helpers (FFMA2: 2 MACs per FMA-pipe issue) ----
__device__ __forceinline__ ull pack2(float lo, float hi) {
    ull r; asm("mov.b64 %0, {%1, %2};" : "=l"(r) : "f"(lo), "f"(hi)); return r;
}
__device__ __forceinline__ ull dup2(float x) {
    ull r; asm("mov.b64 %0, {%1, %1};" : "=l"(r) : "f"(x)); return r;
}
__device__ __forceinline__ ull ffma2(ull a, ull b, ull c) {
    ull d; asm("fma.rn.f32x2 %0, %1, %2, %3;" : "=l"(d) : "l"(a), "l"(b), "l"(c)); return d;
}
__device__ __forceinline__ float2 unpk2(ull v) {
    float2 f; asm("mov.b64 {%0, %1}, %2;" : "=f"(f.x), "=f"(f.y) : "l"(v)); return f;
}
__device__ __forceinline__ float tanha(float x) {
    float y; asm("tanh.approx.f32 %0, %1;" : "=f"(y) : "f"(x)); return y;
}

// ============================================================================
// Fused kernel A (unchanged): pair-tile scores + elementwise att.
// ============================================================================
__global__ __launch_bounds__(128) void kA(const float* __restrict__ q,
                                          const float* __restrict__ kk,
                                          float* __restrict__ att,
                                          const float* __restrict__ p0,
                                          const float* __restrict__ p1,
                                          const float* __restrict__ p2,
                                          const float* __restrict__ p3) {
    __shared__ float sb_[8704];
    const int p = blockIdx.x, bh = blockIdx.y;
    const int b = bh >> 3, h = bh & 7;
    int i = (int)((__fsqrt_rn(8.0f * p + 1.0f) - 1.0f) * 0.5f);
    while ((i + 1) * (i + 2) / 2 <= p) i++;
    while (i * (i + 1) / 2 > p) i--;
    const int j = p - i * (i + 1) / 2;

    const int tid = threadIdx.x;
    const int half = tid >> 6, t6 = tid & 63;
    const int l0 = (t6 >> 3) << 3, s0 = (t6 & 7) << 3;

    float* Qi = sb_;
    float* Kj = sb_ + 2176;
    float* Qj = sb_ + 4352;
    float* Ki = sb_ + 6528;
    const float* A_ = half ? Qj : Qi;
    const float* B_ = half ? Ki : Kj;

    ull acc[8][4];
    #pragma unroll
    for (int r = 0; r < 8; r++)
        #pragma unroll
        for (int c = 0; c < 4; c++) acc[r][c] = 0ull;

    for (int c = 0; c < 2; c++) {
        __syncthreads();
        const int e0c = c << 5;
        #pragma unroll
        for (int t = tid; t < 2048; t += 128) {
            int tile = t >> 9, r = (t >> 3) & 63, e4 = (t & 7) << 2;
            int row; const float* src; float* dst;
            if (tile == 0)      { row = i * 64 + r; src = q;  dst = Qi; }
            else if (tile == 1) { row = j * 64 + r; src = kk; dst = Kj; }
            else if (tile == 2) { row = j * 64 + r; src = q;  dst = Qj; }
            else                { row = i * 64 + r; src = kk; dst = Ki; }
            float4 v = *(const float4*)(src + (((size_t)(b * LLEN + row)) * 8 + h) * 64 + e0c + e4);
            dst[(e4 + 0) * 68 + r] = v.x; dst[(e4 + 1) * 68 + r] = v.y;
            dst[(e4 + 2) * 68 + r] = v.z; dst[(e4 + 3) * 68 + r] = v.w;
        }
        __syncthreads();
        #pragma unroll 8
        for (int e = 0; e < 32; e++) {
            float4 a0 = *(const float4*)(A_ + e * 68 + l0);
            float4 a1 = *(const float4*)(A_ + e * 68 + l0 + 4);
            float4 b0 = *(const float4*)(B_ + e * 68 + s0);
            float4 b1 = *(const float4*)(B_ + e * 68 + s0 + 4);
            ull bp[4] = {pack2(b0.x, b0.y), pack2(b0.z, b0.w),
                         pack2(b1.x, b1.y), pack2(b1.z, b1.w)};
            float av[8] = {a0.x, a0.y, a0.z, a0.w, a1.x, a1.y, a1.z, a1.w};
            #pragma unroll
            for (int r = 0; r < 8; r++) {
                ull ad = dup2(av[r]);
                #pragma unroll
                for (int cc = 0; cc < 4; cc++) acc[r][cc] = ffma2(ad, bp[cc], acc[r][cc]);
            }
        }
    }

    __syncthreads();
    float* C1 = sb_;
    float* C2 = sb_ + 4352;
    float* Cm = half ? C2 : C1;
    #pragma unroll
    for (int r = 0; r < 8; r++) {
        float o[8];
        #pragma unroll
        for (int cc = 0; cc < 4; cc++) {
            float2 f = unpk2(acc[r][cc]);
            o[2 * cc] = f.x * 0.125f; o[2 * cc + 1] = f.y * 0.125f;
        }
        float* pd = Cm + (l0 + r) * 68 + s0;
        *(float4*)pd       = make_float4(o[0], o[1], o[2], o[3]);
        *(float4*)(pd + 4) = make_float4(o[4], o[5], o[6], o[7]);
    }
    __syncthreads();

    const float gg = fminf(fmaxf(__expf(*p0), 1e-3f), 20.0f);
    const float tg = fminf(fmaxf(__expf(*p1), 1e-3f), 10.0f);
    const float gd = fminf(fmaxf(__expf(*p2), 1e-3f), 20.0f);
    const float td = fminf(fmaxf(__expf(*p3), 1e-3f), 10.0f);
    const float itg = 1.0f / tg, itd = 1.0f / td, gdd = gd / td;

    if (!(half && i == j)) {
        const int r = t6;
        const float* Cown = half ? C2 : C1;
        const float* Coth = half ? C1 : C2;
        const int lg  = (half ? j : i) * 64 + r;
        const int sg0 = (half ? i : j) * 64;
        float* arow = att + ((size_t)bh * LLEN + lg) * LLEN + sg0;
        const bool dg = (i == j);
        #pragma unroll
        for (int s4 = 0; s4 < 64; s4 += 4) {
            float4 g1 = *(const float4*)(Cown + r * 68 + s4);
            float o[4];
            #pragma unroll
            for (int v = 0; v < 4; v++) {
                float g1v = (&g1.x)[v];
                float g2v = Coth[(s4 + v) * 68 + r];
                float Ss = 0.5f * (g1v + g2v);
                float Aa = 0.5f * (g1v - g2v);
                float t1 = tanha(Ss * itg);
                float t2 = tanha(Aa * itd);
                float s1 = fmaf(tanha(0.5f * gg * t1), 0.5f, 0.5f);
                float s2 = fmaf(tanha(0.5f * gd * t2), 0.5f, 0.5f);
                float m = s1 * s2;
                if (dg && (s4 + v) == r) m = 0.0f;
                o[v] = fmaxf(tanha(Aa * gdd), 0.0f) * m;
            }
            *(float4*)(arow + s4) = make_float4(o[0], o[1], o[2], o[3]);
        }
    }
}

// ============================================================================
// K3 (R2 shape + split-K over s): 128-row l-tile, 8x8 micro, 128 threads.
// Each block handles 256 s-values (8 chunks of 32) -> partials to scratch.
// grid (8 l-tiles, 16 bh, 4 splits) = 512 blocks (3x the resident warps of R2).
// ============================================================================
__global__ __launch_bounds__(128) void k3_av(const float* __restrict__ att,
                                             const float* __restrict__ val,
                                             float* __restrict__ pv,
                                             float* __restrict__ pe) {
    __shared__ float As[128][36];
    __shared__ float Vs[32][68];
    const int bh = blockIdx.y, b = bh >> 3, h = bh & 7;
    const int lb = blockIdx.x << 7;
    const int sp = blockIdx.z;
    const int tid = threadIdx.x;
    const int eg = tid & 7, lgp = tid >> 3;
    const int lrow0 = lgp << 3, e0 = eg << 3;

    ull acc[8][4];
    #pragma unroll
    for (int r = 0; r < 8; r++)
        #pragma unroll
        for (int c = 0; c < 4; c++) acc[r][c] = 0ull;
    float entacc = 0.0f;

    const float* attbase = att + ((size_t)bh * LLEN + lb) * LLEN;

    const int cb0 = sp << 3;
    for (int cb = cb0; cb < cb0 + 8; cb++) {
        const int sb = cb << 5;
        __syncthreads();
        #pragma unroll
        for (int t = tid; t < 1024; t += 128) {
            int rr = t >> 3, c4 = (t & 7) << 2;
            *(float4*)&As[rr][c4] = *(const float4*)(attbase + (size_t)rr * LLEN + sb + c4);
        }
        #pragma unroll
        for (int t = tid; t < 512; t += 128) {
            int rr = t >> 4, c4 = (t & 15) << 2;
            *(float4*)&Vs[rr][c4] = *(const float4*)(val + (((size_t)(b * LLEN + sb + rr)) * 8 + h) * 64 + c4);
        }
        __syncthreads();

        #pragma unroll
        for (int s4 = 0; s4 < 32; s4 += 4) {
            float4 a4[8];
            #pragma unroll
            for (int r = 0; r < 8; r++) a4[r] = *(const float4*)&As[lrow0 + r][s4];
            #pragma unroll
            for (int u = 0; u < 4; u++) {
                int ss = s4 + u;
                float4 w0 = *(const float4*)&Vs[ss][e0];
                float4 w1 = *(const float4*)&Vs[ss][e0 + 4];
                ull v2[4] = {pack2(w0.x, w0.y), pack2(w0.z, w0.w),
                             pack2(w1.x, w1.y), pack2(w1.z, w1.w)};
                #pragma unroll
                for (int r = 0; r < 8; r++) {
                    ull ad = dup2((&a4[r].x)[u]);
                    #pragma unroll
                    for (int c = 0; c < 4; c++) acc[r][c] = ffma2(ad, v2[c], acc[r][c]);
                }
            }
        }
        // entropy partial: this thread owns att row (lb+tid)
        #pragma unroll
        for (int s4 = 0; s4 < 32; s4 += 4) {
            float4 a = *(const float4*)&As[tid][s4];
            entacc += a.x * __logf(fmaxf(a.x, 1e-8f));
            entacc += a.y * __logf(fmaxf(a.y, 1e-8f));
            entacc += a.z * __logf(fmaxf(a.z, 1e-8f));
            entacc += a.w * __logf(fmaxf(a.w, 1e-8f));
        }
    }

    pe[(size_t)sp * ENT_ELEMS_C + (size_t)bh * LLEN + lb + tid] = entacc;

    float* pvs = pv + (size_t)sp * V_ELEMS_C;
    #pragma unroll
    for (int r = 0; r < 8; r++) {
        int l = lb + lrow0 + r;
        float o[8];
        #pragma unroll
        for (int c = 0; c < 4; c++) {
            float2 f = unpk2(acc[r][c]);
            o[2 * c] = f.x; o[2 * c + 1] = f.y;
        }
        float* pd = pvs + (((size_t)(b * LLEN + l)) * 8 + h) * 64 + e0;
        *(float4*)pd       = make_float4(o[0], o[1], o[2], o[3]);
        *(float4*)(pd + 4) = make_float4(o[4], o[5], o[6], o[7]);
    }
}

// ============================================================================
// K4: deterministic split reduction (fixed summation order).
// ============================================================================
__global__ __launch_bounds__(256) void k4_reduce(const float* __restrict__ pv,
                                                 const float* __restrict__ pe,
                                                 float* __restrict__ vout,
                                                 float* __restrict__ ent) {
    int idx = blockIdx.x * 256 + threadIdx.x;
    if (idx < V_ELEMS_C) {
        float s = pv[idx];
        s += pv[idx + V_ELEMS_C];
        s += pv[idx + 2 * V_ELEMS_C];
        s += pv[idx + 3 * V_ELEMS_C];
        vout[idx] = s;
    } else {
        int e = idx - V_ELEMS_C;
        if (e < ENT_ELEMS_C) {
            float s = pe[e];
            s += pe[e + ENT_ELEMS_C];
            s += pe[e + 2 * ENT_ELEMS_C];
            s += pe[e + 3 * ENT_ELEMS_C];
            ent[e] = -s;
        }
    }
}

// ============================================================================
// Launch: kA -> k3 -> k4. Graph-capturable, no alloc.
// ============================================================================
extern "C" void kernel_launch(void* const* d_in, const int* in_sizes, int n_in,
                              void* d_out, int out_size) {
    const float* q = (const float*)d_in[0];
    const float* k = (const float*)d_in[1];
    const float* v = (const float*)d_in[2];
    const float* lgg = (const float*)d_in[n_in - 4];
    const float* ltg = (const float*)d_in[n_in - 3];
    const float* lgd = (const float*)d_in[n_in - 2];
    const float* ltd = (const float*)d_in[n_in - 1];

    const long V_ELEMS   = V_ELEMS_C;
    const long ATT_ELEMS = (long)NBH * LLEN * LLEN;
    const long ENT_ELEMS = ENT_ELEMS_C;

    float* out = (float*)d_out;
    float* vptr = out;
    float* attp;
    float* entp;
    if ((long)out_size >= V_ELEMS + ATT_ELEMS + ENT_ELEMS) {
        attp = out + V_ELEMS;
        entp = out + V_ELEMS + ATT_ELEMS;
    } else {
        void* p1 = nullptr; void* p2 = nullptr;
        cudaGetSymbolAddress(&p1, g_att_fb);
        cudaGetSymbolAddress(&p2, g_ent_fb);
        attp = (float*)p1;
        entp = (float*)p2;
    }

    void* ppv = nullptr; void* ppe = nullptr;
    cudaGetSymbolAddress(&ppv, g_pv);
    cudaGetSymbolAddress(&ppe, g_pe);

    kA<<<dim3(136, 16), 128>>>(q, k, attp, lgg, ltg, lgd, ltd);
    k3_av<<<dim3(8, 16, NSPLIT), 128>>>(attp, v, (float*)ppv, (float*)ppe);
    k4_reduce<<<(V_ELEMS_C + ENT_ELEMS_C) / 256, 256>>>((const float*)ppv, (const float*)ppe, vptr, entp);
}

// round 9
// speedup vs baseline: 1.6180x; 1.0840x over previous
#include <cuda_runtime.h>
#include <cstdint>

#define LLEN 1024
#define NBH 16
#define NSPLIT 8
#define V_ELEMS_C 1048576
#define ENT_ELEMS_C 16384

typedef unsigned long long ull;

// Fallbacks in case d_out only holds V (defensive vs. output-layout surprises).
__device__ float g_att_fb[(size_t)NBH * LLEN * LLEN];
__device__ float g_ent_fb[(size_t)NBH * LLEN];
// Split-K partials (deterministic two-pass reduction).
__device__ float g_pv[(size_t)NSPLIT * V_ELEMS_C];
__device__ float g_pe[(size_t)NSPLIT * ENT_ELEMS_C];

// ---- packed f32x2 helpers ----
__device__ __forceinline__ ull pack2(float lo, float hi) {
    ull r; asm("mov.b64 %0, {%1, %2};" : "=l"(r) : "f"(lo), "f"(hi)); return r;
}
__device__ __forceinline__ ull dup2(float x) {
    ull r; asm("mov.b64 %0, {%1, %1};" : "=l"(r) : "f"(x)); return r;
}
__device__ __forceinline__ ull ffma2(ull a, ull b, ull c) {
    ull d; asm("fma.rn.f32x2 %0, %1, %2, %3;" : "=l"(d) : "l"(a), "l"(b), "l"(c)); return d;
}
__device__ __forceinline__ float2 unpk2(ull v) {
    float2 f; asm("mov.b64 {%0, %1}, %2;" : "=f"(f.x), "=f"(f.y) : "l"(v)); return f;
}
__device__ __forceinline__ float tanha(float x) {
    float y; asm("tanh.approx.f32 %0, %1;" : "=f"(y) : "f"(x)); return y;
}

// ============================================================================
// Fused kernel A: pair-tile scores + elementwise att.
// R8 change: XOR-swizzled e-major staging (row' = row ^ (e & 28)) makes the
// transposed STS conflict-free while keeping GEMM fragment reads as LDS.128.
// ============================================================================
__global__ __launch_bounds__(128) void kA(const float* __restrict__ q,
                                          const float* __restrict__ kk,
                                          float* __restrict__ att,
                                          const float* __restrict__ p0,
                                          const float* __restrict__ p1,
                                          const float* __restrict__ p2,
                                          const float* __restrict__ p3) {
    __shared__ float sb_[8704];
    const int p = blockIdx.x, bh = blockIdx.y;
    const int b = bh >> 3, h = bh & 7;
    int i = (int)((__fsqrt_rn(8.0f * p + 1.0f) - 1.0f) * 0.5f);
    while ((i + 1) * (i + 2) / 2 <= p) i++;
    while (i * (i + 1) / 2 > p) i--;
    const int j = p - i * (i + 1) / 2;

    const int tid = threadIdx.x;
    const int half = tid >> 6, t6 = tid & 63;
    const int l0 = (t6 >> 3) << 3, s0 = (t6 & 7) << 3;

    float* Qi = sb_;
    float* Kj = sb_ + 2176;
    float* Qj = sb_ + 4352;
    float* Ki = sb_ + 6528;
    const float* A_ = half ? Qj : Qi;
    const float* B_ = half ? Ki : Kj;

    ull acc[8][4];
    #pragma unroll
    for (int r = 0; r < 8; r++)
        #pragma unroll
        for (int c = 0; c < 4; c++) acc[r][c] = 0ull;

    for (int c = 0; c < 2; c++) {
        __syncthreads();
        const int e0c = c << 5;
        #pragma unroll
        for (int t = tid; t < 2048; t += 128) {
            int tile = t >> 9, r = (t >> 3) & 63, e4 = (t & 7) << 2;
            int row; const float* src; float* dst;
            if (tile == 0)      { row = i * 64 + r; src = q;  dst = Qi; }
            else if (tile == 1) { row = j * 64 + r; src = kk; dst = Kj; }
            else if (tile == 2) { row = j * 64 + r; src = q;  dst = Qj; }
            else                { row = i * 64 + r; src = kk; dst = Ki; }
            float4 v = *(const float4*)(src + (((size_t)(b * LLEN + row)) * 8 + h) * 64 + e0c + e4);
            const int rs = r ^ e4;   // e4 in {0,4,...,28}: swizzle bits 2-4 -> conflict-free STS
            dst[(e4 + 0) * 68 + rs] = v.x; dst[(e4 + 1) * 68 + rs] = v.y;
            dst[(e4 + 2) * 68 + rs] = v.z; dst[(e4 + 3) * 68 + rs] = v.w;
        }
        __syncthreads();
        #pragma unroll 8
        for (int e = 0; e < 32; e++) {
            const int fe = e & 28;
            const float* Ae = A_ + e * 68;
            const float* Be = B_ + e * 68;
            float4 a0 = *(const float4*)(Ae + (l0 ^ fe));
            float4 a1 = *(const float4*)(Ae + ((l0 + 4) ^ fe));
            float4 b0 = *(const float4*)(Be + (s0 ^ fe));
            float4 b1 = *(const float4*)(Be + ((s0 + 4) ^ fe));
            ull bp[4] = {pack2(b0.x, b0.y), pack2(b0.z, b0.w),
                         pack2(b1.x, b1.y), pack2(b1.z, b1.w)};
            float av[8] = {a0.x, a0.y, a0.z, a0.w, a1.x, a1.y, a1.z, a1.w};
            #pragma unroll
            for (int r = 0; r < 8; r++) {
                ull ad = dup2(av[r]);
                #pragma unroll
                for (int cc = 0; cc < 4; cc++) acc[r][cc] = ffma2(ad, bp[cc], acc[r][cc]);
            }
        }
    }

    __syncthreads();
    float* C1 = sb_;
    float* C2 = sb_ + 4352;
    float* Cm = half ? C2 : C1;
    #pragma unroll
    for (int r = 0; r < 8; r++) {
        float o[8];
        #pragma unroll
        for (int cc = 0; cc < 4; cc++) {
            float2 f = unpk2(acc[r][cc]);
            o[2 * cc] = f.x * 0.125f; o[2 * cc + 1] = f.y * 0.125f;
        }
        float* pd = Cm + (l0 + r) * 68 + s0;
        *(float4*)pd       = make_float4(o[0], o[1], o[2], o[3]);
        *(float4*)(pd + 4) = make_float4(o[4], o[5], o[6], o[7]);
    }
    __syncthreads();

    const float gg = fminf(fmaxf(__expf(*p0), 1e-3f), 20.0f);
    const float tg = fminf(fmaxf(__expf(*p1), 1e-3f), 10.0f);
    const float gd = fminf(fmaxf(__expf(*p2), 1e-3f), 20.0f);
    const float td = fminf(fmaxf(__expf(*p3), 1e-3f), 10.0f);
    const float itg = 1.0f / tg, itd = 1.0f / td, gdd = gd / td;

    if (!(half && i == j)) {
        const int r = t6;
        const float* Cown = half ? C2 : C1;
        const float* Coth = half ? C1 : C2;
        const int lg  = (half ? j : i) * 64 + r;
        const int sg0 = (half ? i : j) * 64;
        float* arow = att + ((size_t)bh * LLEN + lg) * LLEN + sg0;
        const bool dg = (i == j);
        #pragma unroll
        for (int s4 = 0; s4 < 64; s4 += 4) {
            float4 g1 = *(const float4*)(Cown + r * 68 + s4);
            float o[4];
            #pragma unroll
            for (int v = 0; v < 4; v++) {
                float g1v = (&g1.x)[v];
                float g2v = Coth[(s4 + v) * 68 + r];
                float Ss = 0.5f * (g1v + g2v);
                float Aa = 0.5f * (g1v - g2v);
                float t1 = tanha(Ss * itg);
                float t2 = tanha(Aa * itd);
                float s1 = fmaf(tanha(0.5f * gg * t1), 0.5f, 0.5f);
                float s2 = fmaf(tanha(0.5f * gd * t2), 0.5f, 0.5f);
                float m = s1 * s2;
                if (dg && (s4 + v) == r) m = 0.0f;
                o[v] = fmaxf(tanha(Aa * gdd), 0.0f) * m;
            }
            *(float4*)(arow + s4) = make_float4(o[0], o[1], o[2], o[3]);
        }
    }
}

// ============================================================================
// K3 (split-K over s, NSPLIT=8): 128-row l-tile, 8x8 micro, 128 threads.
// Each block handles 128 s-values (4 chunks of 32) -> partials to scratch.
// grid (8 l-tiles, 16 bh, 8 splits) = 1024 blocks (6.9 waves: tiny tail).
// ============================================================================
__global__ __launch_bounds__(128) void k3_av(const float* __restrict__ att,
                                             const float* __restrict__ val,
                                             float* __restrict__ pv,
                                             float* __restrict__ pe) {
    __shared__ float As[128][36];
    __shared__ float Vs[32][68];
    const int bh = blockIdx.y, b = bh >> 3, h = bh & 7;
    const int lb = blockIdx.x << 7;
    const int sp = blockIdx.z;
    const int tid = threadIdx.x;
    const int eg = tid & 7, lgp = tid >> 3;
    const int lrow0 = lgp << 3, e0 = eg << 3;

    ull acc[8][4];
    #pragma unroll
    for (int r = 0; r < 8; r++)
        #pragma unroll
        for (int c = 0; c < 4; c++) acc[r][c] = 0ull;
    float entacc = 0.0f;

    const float* attbase = att + ((size_t)bh * LLEN + lb) * LLEN;

    const int cb0 = sp << 2;
    for (int cb = cb0; cb < cb0 + 4; cb++) {
        const int sb = cb << 5;
        __syncthreads();
        #pragma unroll
        for (int t = tid; t < 1024; t += 128) {
            int rr = t >> 3, c4 = (t & 7) << 2;
            *(float4*)&As[rr][c4] = *(const float4*)(attbase + (size_t)rr * LLEN + sb + c4);
        }
        #pragma unroll
        for (int t = tid; t < 512; t += 128) {
            int rr = t >> 4, c4 = (t & 15) << 2;
            *(float4*)&Vs[rr][c4] = *(const float4*)(val + (((size_t)(b * LLEN + sb + rr)) * 8 + h) * 64 + c4);
        }
        __syncthreads();

        #pragma unroll
        for (int s4 = 0; s4 < 32; s4 += 4) {
            float4 a4[8];
            #pragma unroll
            for (int r = 0; r < 8; r++) a4[r] = *(const float4*)&As[lrow0 + r][s4];
            #pragma unroll
            for (int u = 0; u < 4; u++) {
                int ss = s4 + u;
                float4 w0 = *(const float4*)&Vs[ss][e0];
                float4 w1 = *(const float4*)&Vs[ss][e0 + 4];
                ull v2[4] = {pack2(w0.x, w0.y), pack2(w0.z, w0.w),
                             pack2(w1.x, w1.y), pack2(w1.z, w1.w)};
                #pragma unroll
                for (int r = 0; r < 8; r++) {
                    ull ad = dup2((&a4[r].x)[u]);
                    #pragma unroll
                    for (int c = 0; c < 4; c++) acc[r][c] = ffma2(ad, v2[c], acc[r][c]);
                }
            }
        }
        #pragma unroll
        for (int s4 = 0; s4 < 32; s4 += 4) {
            float4 a = *(const float4*)&As[tid][s4];
            entacc += a.x * __logf(fmaxf(a.x, 1e-8f));
            entacc += a.y * __logf(fmaxf(a.y, 1e-8f));
            entacc += a.z * __logf(fmaxf(a.z, 1e-8f));
            entacc += a.w * __logf(fmaxf(a.w, 1e-8f));
        }
    }

    pe[(size_t)sp * ENT_ELEMS_C + (size_t)bh * LLEN + lb + tid] = entacc;

    float* pvs = pv + (size_t)sp * V_ELEMS_C;
    #pragma unroll
    for (int r = 0; r < 8; r++) {
        int l = lb + lrow0 + r;
        float o[8];
        #pragma unroll
        for (int c = 0; c < 4; c++) {
            float2 f = unpk2(acc[r][c]);
            o[2 * c] = f.x; o[2 * c + 1] = f.y;
        }
        float* pd = pvs + (((size_t)(b * LLEN + l)) * 8 + h) * 64 + e0;
        *(float4*)pd       = make_float4(o[0], o[1], o[2], o[3]);
        *(float4*)(pd + 4) = make_float4(o[4], o[5], o[6], o[7]);
    }
}

// ============================================================================
// K4: deterministic split reduction (fixed summation order, 8 partials).
// ============================================================================
__global__ __launch_bounds__(256) void k4_reduce(const float* __restrict__ pv,
                                                 const float* __restrict__ pe,
                                                 float* __restrict__ vout,
                                                 float* __restrict__ ent) {
    int idx = blockIdx.x * 256 + threadIdx.x;
    if (idx < V_ELEMS_C) {
        float s = pv[idx];
        #pragma unroll
        for (int m = 1; m < NSPLIT; m++) s += pv[idx + (size_t)m * V_ELEMS_C];
        vout[idx] = s;
    } else {
        int e = idx - V_ELEMS_C;
        if (e < ENT_ELEMS_C) {
            float s = pe[e];
            #pragma unroll
            for (int m = 1; m < NSPLIT; m++) s += pe[e + (size_t)m * ENT_ELEMS_C];
            ent[e] = -s;
        }
    }
}

// ============================================================================
// Launch: kA -> k3 -> k4. Graph-capturable, no alloc.
// ============================================================================
extern "C" void kernel_launch(void* const* d_in, const int* in_sizes, int n_in,
                              void* d_out, int out_size) {
    const float* q = (const float*)d_in[0];
    const float* k = (const float*)d_in[1];
    const float* v = (const float*)d_in[2];
    const float* lgg = (const float*)d_in[n_in - 4];
    const float* ltg = (const float*)d_in[n_in - 3];
    const float* lgd = (const float*)d_in[n_in - 2];
    const float* ltd = (const float*)d_in[n_in - 1];

    const long V_ELEMS   = V_ELEMS_C;
    const long ATT_ELEMS = (long)NBH * LLEN * LLEN;
    const long ENT_ELEMS = ENT_ELEMS_C;

    float* out = (float*)d_out;
    float* vptr = out;
    float* attp;
    float* entp;
    if ((long)out_size >= V_ELEMS + ATT_ELEMS + ENT_ELEMS) {
        attp = out + V_ELEMS;
        entp = out + V_ELEMS + ATT_ELEMS;
    } else {
        void* p1 = nullptr; void* p2 = nullptr;
        cudaGetSymbolAddress(&p1, g_att_fb);
        cudaGetSymbolAddress(&p2, g_ent_fb);
        attp = (float*)p1;
        entp = (float*)p2;
    }

    void* ppv = nullptr; void* ppe = nullptr;
    cudaGetSymbolAddress(&ppv, g_pv);
    cudaGetSymbolAddress(&ppe, g_pe);

    kA<<<dim3(136, 16), 128>>>(q, k, attp, lgg, ltg, lgd, ltd);
    k3_av<<<dim3(8, 16, NSPLIT), 128>>>(attp, v, (float*)ppv, (float*)ppe);
    k4_reduce<<<(V_ELEMS_C + ENT_ELEMS_C + 255) / 256, 256>>>((const float*)ppv, (const float*)ppe, vptr, entp);
}

// round 11
// speedup vs baseline: 1.7203x; 1.0632x over previous
#include <cuda_runtime.h>
#include <cstdint>

#define LLEN 1024
#define NBH 16
#define NSPLIT 8
#define V_ELEMS_C 1048576
#define ENT_ELEMS_C 16384

typedef unsigned long long ull;

// Fallbacks in case d_out only holds V (defensive vs. output-layout surprises).
__device__ float g_att_fb[(size_t)NBH * LLEN * LLEN];
__device__ float g_ent_fb[(size_t)NBH * LLEN];
// Split-K partials (deterministic two-pass reduction).
__device__ float g_pv[(size_t)NSPLIT * V_ELEMS_C];
__device__ float g_pe[(size_t)NSPLIT * ENT_ELEMS_C];

// ---- packed f32x2 helpers ----
__device__ __forceinline__ ull pack2(float lo, float hi) {
    ull r; asm("mov.b64 %0, {%1, %2};" : "=l"(r) : "f"(lo), "f"(hi)); return r;
}
__device__ __forceinline__ ull dup2(float x) {
    ull r; asm("mov.b64 %0, {%1, %1};" : "=l"(r) : "f"(x)); return r;
}
__device__ __forceinline__ ull ffma2(ull a, ull b, ull c) {
    ull d; asm("fma.rn.f32x2 %0, %1, %2, %3;" : "=l"(d) : "l"(a), "l"(b), "l"(c)); return d;
}
__device__ __forceinline__ float2 unpk2(ull v) {
    float2 f; asm("mov.b64 {%0, %1}, %2;" : "=f"(f.x), "=f"(f.y) : "l"(v)); return f;
}
__device__ __forceinline__ float tanha(float x) {
    float y; asm("tanh.approx.f32 %0, %1;" : "=f"(y) : "f"(x)); return y;
}

// ============================================================================
// Fused kernel A: pair-tile scores + elementwise att.
// R10: __launch_bounds__(128,4) reg cap (3->4 blocks/SM); diagonal-pair
// half-1 GEMM skip (C2==C1 when i==j).
// ============================================================================
__global__ __launch_bounds__(128, 4) void kA(const float* __restrict__ q,
                                             const float* __restrict__ kk,
                                             float* __restrict__ att,
                                             const float* __restrict__ p0,
                                             const float* __restrict__ p1,
                                             const float* __restrict__ p2,
                                             const float* __restrict__ p3) {
    __shared__ float sb_[8704];
    const int p = blockIdx.x, bh = blockIdx.y;
    const int b = bh >> 3, h = bh & 7;
    int i = (int)((__fsqrt_rn(8.0f * p + 1.0f) - 1.0f) * 0.5f);
    while ((i + 1) * (i + 2) / 2 <= p) i++;
    while (i * (i + 1) / 2 > p) i--;
    const int j = p - i * (i + 1) / 2;

    const int tid = threadIdx.x;
    const int half = tid >> 6, t6 = tid & 63;
    const int l0 = (t6 >> 3) << 3, s0 = (t6 & 7) << 3;

    float* Qi = sb_;
    float* Kj = sb_ + 2176;
    float* Qj = sb_ + 4352;
    float* Ki = sb_ + 6528;
    const float* A_ = half ? Qj : Qi;
    const float* B_ = half ? Ki : Kj;

    // Diagonal pair: C2 == C1, half 1's GEMM is redundant (skip compute only;
    // all threads still execute staging + barriers).
    const bool skip_gemm = (half && i == j);

    ull acc[8][4];
    #pragma unroll
    for (int r = 0; r < 8; r++)
        #pragma unroll
        for (int c = 0; c < 4; c++) acc[r][c] = 0ull;

    for (int c = 0; c < 2; c++) {
        __syncthreads();
        const int e0c = c << 5;
        #pragma unroll
        for (int t = tid; t < 2048; t += 128) {
            int tile = t >> 9, r = (t >> 3) & 63, e4 = (t & 7) << 2;
            int row; const float* src; float* dst;
            if (tile == 0)      { row = i * 64 + r; src = q;  dst = Qi; }
            else if (tile == 1) { row = j * 64 + r; src = kk; dst = Kj; }
            else if (tile == 2) { row = j * 64 + r; src = q;  dst = Qj; }
            else                { row = i * 64 + r; src = kk; dst = Ki; }
            float4 v = *(const float4*)(src + (((size_t)(b * LLEN + row)) * 8 + h) * 64 + e0c + e4);
            const int rs = r ^ e4;   // conflict-free transposed STS
            dst[(e4 + 0) * 68 + rs] = v.x; dst[(e4 + 1) * 68 + rs] = v.y;
            dst[(e4 + 2) * 68 + rs] = v.z; dst[(e4 + 3) * 68 + rs] = v.w;
        }
        __syncthreads();
        if (!skip_gemm) {
            #pragma unroll 8
            for (int e = 0; e < 32; e++) {
                const int fe = e & 28;
                const float* Ae = A_ + e * 68;
                const float* Be = B_ + e * 68;
                float4 a0 = *(const float4*)(Ae + (l0 ^ fe));
                float4 a1 = *(const float4*)(Ae + ((l0 + 4) ^ fe));
                float4 b0 = *(const float4*)(Be + (s0 ^ fe));
                float4 b1 = *(const float4*)(Be + ((s0 + 4) ^ fe));
                ull bp[4] = {pack2(b0.x, b0.y), pack2(b0.z, b0.w),
                             pack2(b1.x, b1.y), pack2(b1.z, b1.w)};
                float av[8] = {a0.x, a0.y, a0.z, a0.w, a1.x, a1.y, a1.z, a1.w};
                #pragma unroll
                for (int r = 0; r < 8; r++) {
                    ull ad = dup2(av[r]);
                    #pragma unroll
                    for (int cc = 0; cc < 4; cc++) acc[r][cc] = ffma2(ad, bp[cc], acc[r][cc]);
                }
            }
        }
    }

    __syncthreads();
    float* C1 = sb_;
    float* C2 = sb_ + 4352;
    if (!skip_gemm) {
        float* Cm = half ? C2 : C1;
        #pragma unroll
        for (int r = 0; r < 8; r++) {
            float o[8];
            #pragma unroll
            for (int cc = 0; cc < 4; cc++) {
                float2 f = unpk2(acc[r][cc]);
                o[2 * cc] = f.x * 0.125f; o[2 * cc + 1] = f.y * 0.125f;
            }
            float* pd = Cm + (l0 + r) * 68 + s0;
            *(float4*)pd       = make_float4(o[0], o[1], o[2], o[3]);
            *(float4*)(pd + 4) = make_float4(o[4], o[5], o[6], o[7]);
        }
    }
    __syncthreads();
    // For i==j, C2 was never written: phase-2 half 1 is skipped, and half 0's
    // Coth must point at C1 (C2 would be stale).
    const bool dg = (i == j);

    const float gg = fminf(fmaxf(__expf(*p0), 1e-3f), 20.0f);
    const float tg = fminf(fmaxf(__expf(*p1), 1e-3f), 10.0f);
    const float gd = fminf(fmaxf(__expf(*p2), 1e-3f), 20.0f);
    const float td = fminf(fmaxf(__expf(*p3), 1e-3f), 10.0f);
    const float itg = 1.0f / tg, itd = 1.0f / td, gdd = gd / td;

    if (!(half && dg)) {
        const int r = t6;
        const float* Cown = half ? C2 : C1;
        const float* Coth = dg ? C1 : (half ? C1 : C2);
        const int lg  = (half ? j : i) * 64 + r;
        const int sg0 = (half ? i : j) * 64;
        float* arow = att + ((size_t)bh * LLEN + lg) * LLEN + sg0;
        #pragma unroll
        for (int s4 = 0; s4 < 64; s4 += 4) {
            float4 g1 = *(const float4*)(Cown + r * 68 + s4);
            float o[4];
            #pragma unroll
            for (int v = 0; v < 4; v++) {
                float g1v = (&g1.x)[v];
                float g2v = Coth[(s4 + v) * 68 + r];
                float Ss = 0.5f * (g1v + g2v);
                float Aa = 0.5f * (g1v - g2v);
                float t1 = tanha(Ss * itg);
                float t2 = tanha(Aa * itd);
                float s1 = fmaf(tanha(0.5f * gg * t1), 0.5f, 0.5f);
                float s2 = fmaf(tanha(0.5f * gd * t2), 0.5f, 0.5f);
                float m = s1 * s2;
                if (dg && (s4 + v) == r) m = 0.0f;
                o[v] = fmaxf(tanha(Aa * gdd), 0.0f) * m;
            }
            *(float4*)(arow + s4) = make_float4(o[0], o[1], o[2], o[3]);
        }
    }
}

// ============================================================================
// K3 (split-K over s, NSPLIT=8) + reg cap for 4 blocks/SM.
// ============================================================================
__global__ __launch_bounds__(128, 4) void k3_av(const float* __restrict__ att,
                                                const float* __restrict__ val,
                                                float* __restrict__ pv,
                                                float* __restrict__ pe) {
    __shared__ float As[128][36];
    __shared__ float Vs[32][68];
    const int bh = blockIdx.y, b = bh >> 3, h = bh & 7;
    const int lb = blockIdx.x << 7;
    const int sp = blockIdx.z;
    const int tid = threadIdx.x;
    const int eg = tid & 7, lgp = tid >> 3;
    const int lrow0 = lgp << 3, e0 = eg << 3;

    ull acc[8][4];
    #pragma unroll
    for (int r = 0; r < 8; r++)
        #pragma unroll
        for (int c = 0; c < 4; c++) acc[r][c] = 0ull;
    float entacc = 0.0f;

    const float* attbase = att + ((size_t)bh * LLEN + lb) * LLEN;

    const int cb0 = sp << 2;
    for (int cb = cb0; cb < cb0 + 4; cb++) {
        const int sb = cb << 5;
        __syncthreads();
        #pragma unroll
        for (int t = tid; t < 1024; t += 128) {
            int rr = t >> 3, c4 = (t & 7) << 2;
            *(float4*)&As[rr][c4] = *(const float4*)(attbase + (size_t)rr * LLEN + sb + c4);
        }
        #pragma unroll
        for (int t = tid; t < 512; t += 128) {
            int rr = t >> 4, c4 = (t & 15) << 2;
            *(float4*)&Vs[rr][c4] = *(const float4*)(val + (((size_t)(b * LLEN + sb + rr)) * 8 + h) * 64 + c4);
        }
        __syncthreads();

        #pragma unroll
        for (int s4 = 0; s4 < 32; s4 += 4) {
            float4 a4[8];
            #pragma unroll
            for (int r = 0; r < 8; r++) a4[r] = *(const float4*)&As[lrow0 + r][s4];
            #pragma unroll
            for (int u = 0; u < 4; u++) {
                int ss = s4 + u;
                float4 w0 = *(const float4*)&Vs[ss][e0];
                float4 w1 = *(const float4*)&Vs[ss][e0 + 4];
                ull v2[4] = {pack2(w0.x, w0.y), pack2(w0.z, w0.w),
                             pack2(w1.x, w1.y), pack2(w1.z, w1.w)};
                #pragma unroll
                for (int r = 0; r < 8; r++) {
                    ull ad = dup2((&a4[r].x)[u]);
                    #pragma unroll
                    for (int c = 0; c < 4; c++) acc[r][c] = ffma2(ad, v2[c], acc[r][c]);
                }
            }
        }
        #pragma unroll
        for (int s4 = 0; s4 < 32; s4 += 4) {
            float4 a = *(const float4*)&As[tid][s4];
            entacc += a.x * __logf(fmaxf(a.x, 1e-8f));
            entacc += a.y * __logf(fmaxf(a.y, 1e-8f));
            entacc += a.z * __logf(fmaxf(a.z, 1e-8f));
            entacc += a.w * __logf(fmaxf(a.w, 1e-8f));
        }
    }

    pe[(size_t)sp * ENT_ELEMS_C + (size_t)bh * LLEN + lb + tid] = entacc;

    float* pvs = pv + (size_t)sp * V_ELEMS_C;
    #pragma unroll
    for (int r = 0; r < 8; r++) {
        int l = lb + lrow0 + r;
        float o[8];
        #pragma unroll
        for (int c = 0; c < 4; c++) {
            float2 f = unpk2(acc[r][c]);
            o[2 * c] = f.x; o[2 * c + 1] = f.y;
        }
        float* pd = pvs + (((size_t)(b * LLEN + l)) * 8 + h) * 64 + e0;
        *(float4*)pd       = make_float4(o[0], o[1], o[2], o[3]);
        *(float4*)(pd + 4) = make_float4(o[4], o[5], o[6], o[7]);
    }
}

// ============================================================================
// K4: deterministic split reduction (fixed summation order, 8 partials).
// ============================================================================
__global__ __launch_bounds__(256) void k4_reduce(const float* __restrict__ pv,
                                                 const float* __restrict__ pe,
                                                 float* __restrict__ vout,
                                                 float* __restrict__ ent) {
    int idx = blockIdx.x * 256 + threadIdx.x;
    if (idx < V_ELEMS_C) {
        float s = pv[idx];
        #pragma unroll
        for (int m = 1; m < NSPLIT; m++) s += pv[idx + (size_t)m * V_ELEMS_C];
        vout[idx] = s;
    } else {
        int e = idx - V_ELEMS_C;
        if (e < ENT_ELEMS_C) {
            float s = pe[e];
            #pragma unroll
            for (int m = 1; m < NSPLIT; m++) s += pe[e + (size_t)m * ENT_ELEMS_C];
            ent[e] = -s;
        }
    }
}

// ============================================================================
// Launch: kA -> k3 -> k4. Graph-capturable, no alloc.
// ============================================================================
extern "C" void kernel_launch(void* const* d_in, const int* in_sizes, int n_in,
                              void* d_out, int out_size) {
    const float* q = (const float*)d_in[0];
    const float* k = (const float*)d_in[1];
    const float* v = (const float*)d_in[2];
    const float* lgg = (const float*)d_in[n_in - 4];
    const float* ltg = (const float*)d_in[n_in - 3];
    const float* lgd = (const float*)d_in[n_in - 2];
    const float* ltd = (const float*)d_in[n_in - 1];

    const long V_ELEMS   = V_ELEMS_C;
    const long ATT_ELEMS = (long)NBH * LLEN * LLEN;
    const long ENT_ELEMS = ENT_ELEMS_C;

    float* out = (float*)d_out;
    float* vptr = out;
    float* attp;
    float* entp;
    if ((long)out_size >= V_ELEMS + ATT_ELEMS + ENT_ELEMS) {
        attp = out + V_ELEMS;
        entp = out + V_ELEMS + ATT_ELEMS;
    } else {
        void* p1 = nullptr; void* p2 = nullptr;
        cudaGetSymbolAddress(&p1, g_att_fb);
        cudaGetSymbolAddress(&p2, g_ent_fb);
        attp = (float*)p1;
        entp = (float*)p2;
    }

    void* ppv = nullptr; void* ppe = nullptr;
    cudaGetSymbolAddress(&ppv, g_pv);
    cudaGetSymbolAddress(&ppe, g_pe);

    kA<<<dim3(136, 16), 128>>>(q, k, attp, lgg, ltg, lgd, ltd);
    k3_av<<<dim3(8, 16, NSPLIT), 128>>>(attp, v, (float*)ppv, (float*)ppe);
    k4_reduce<<<(V_ELEMS_C + ENT_ELEMS_C + 255) / 256, 256>>>((const float*)ppv, (const float*)ppe, vptr, entp);
}

// round 15
// speedup vs baseline: 1.7526x; 1.0188x over previous
#include <cuda_runtime.h>
#include <cstdint>

#define LLEN 1024
#define NBH 16
#define NSPLIT 8
#define V_ELEMS_C 1048576
#define ENT_ELEMS_C 16384

typedef unsigned long long ull;

// Fallbacks in case d_out only holds V (defensive vs. output-layout surprises).
__device__ float g_att_fb[(size_t)NBH * LLEN * LLEN];
__device__ float g_ent_fb[(size_t)NBH * LLEN];
// Split-K partials (deterministic two-pass reduction).
__device__ float g_pv[(size_t)NSPLIT * V_ELEMS_C];
__device__ float g_pe[(size_t)NSPLIT * ENT_ELEMS_C];

// ---- packed f32x2 helpers ----
__device__ __forceinline__ ull pack2(float lo, float hi) {
    ull r; asm("mov.b64 %0, {%1, %2};" : "=l"(r) : "f"(lo), "f"(hi)); return r;
}
__device__ __forceinline__ ull dup2(float x) {
    ull r; asm("mov.b64 %0, {%1, %1};" : "=l"(r) : "f"(x)); return r;
}
__device__ __forceinline__ ull ffma2(ull a, ull b, ull c) {
    ull d; asm("fma.rn.f32x2 %0, %1, %2, %3;" : "=l"(d) : "l"(a), "l"(b), "l"(c)); return d;
}
__device__ __forceinline__ float2 unpk2(ull v) {
    float2 f; asm("mov.b64 {%0, %1}, %2;" : "=f"(f.x), "=f"(f.y) : "l"(v)); return f;
}
__device__ __forceinline__ float tanha(float x) {
    float y; asm("tanh.approx.f32 %0, %1;" : "=f"(y) : "f"(x)); return y;
}

// ============================================================================
// Fused kernel A: pair-tile scores + elementwise att.
// R15: phase-2 sign-split -- one 5-MUFU chain yields BOTH att(i,j)[r,c] and
// att(j,i)[c,r]; aji overwrites C2[c][r] in place (slot read only by this
// thread), then flushed coalesced. Halves kA's MUFU work.
// ============================================================================
__global__ __launch_bounds__(128, 4) void kA(const float* __restrict__ q,
                                             const float* __restrict__ kk,
                                             float* __restrict__ att,
                                             const float* __restrict__ p0,
                                             const float* __restrict__ p1,
                                             const float* __restrict__ p2,
                                             const float* __restrict__ p3) {
    __shared__ float sb_[8704];
    const int p = blockIdx.x, bh = blockIdx.y;
    const int b = bh >> 3, h = bh & 7;
    int i = (int)((__fsqrt_rn(8.0f * p + 1.0f) - 1.0f) * 0.5f);
    while ((i + 1) * (i + 2) / 2 <= p) i++;
    while (i * (i + 1) / 2 > p) i--;
    const int j = p - i * (i + 1) / 2;
    const bool dg = (i == j);

    const int tid = threadIdx.x;
    const int half = tid >> 6, t6 = tid & 63;
    const int l0 = (t6 >> 3) << 3, s0 = (t6 & 7) << 3;

    float* Qi = sb_;
    float* Kj = sb_ + 2176;
    float* Qj = sb_ + 4352;
    float* Ki = sb_ + 6528;
    const float* A_ = half ? Qj : Qi;
    const float* B_ = half ? Ki : Kj;

    const bool skip_gemm = (half && dg);   // diag: C2==C1, half-1 GEMM redundant

    ull acc[8][4];
    #pragma unroll
    for (int r = 0; r < 8; r++)
        #pragma unroll
        for (int c = 0; c < 4; c++) acc[r][c] = 0ull;

    for (int c = 0; c < 2; c++) {
        __syncthreads();
        const int e0c = c << 5;
        #pragma unroll
        for (int t = tid; t < 2048; t += 128) {
            int tile = t >> 9, r = (t >> 3) & 63, e4 = (t & 7) << 2;
            int row; const float* src; float* dst;
            if (tile == 0)      { row = i * 64 + r; src = q;  dst = Qi; }
            else if (tile == 1) { row = j * 64 + r; src = kk; dst = Kj; }
            else if (tile == 2) { row = j * 64 + r; src = q;  dst = Qj; }
            else                { row = i * 64 + r; src = kk; dst = Ki; }
            float4 v = *(const float4*)(src + (((size_t)(b * LLEN + row)) * 8 + h) * 64 + e0c + e4);
            const int rs = r ^ e4;   // conflict-free transposed STS
            dst[(e4 + 0) * 68 + rs] = v.x; dst[(e4 + 1) * 68 + rs] = v.y;
            dst[(e4 + 2) * 68 + rs] = v.z; dst[(e4 + 3) * 68 + rs] = v.w;
        }
        __syncthreads();
        if (!skip_gemm) {
            #pragma unroll 8
            for (int e = 0; e < 32; e++) {
                const int fe = e & 28;
                const float* Ae = A_ + e * 68;
                const float* Be = B_ + e * 68;
                float4 a0 = *(const float4*)(Ae + (l0 ^ fe));
                float4 a1 = *(const float4*)(Ae + ((l0 + 4) ^ fe));
                float4 b0 = *(const float4*)(Be + (s0 ^ fe));
                float4 b1 = *(const float4*)(Be + ((s0 + 4) ^ fe));
                ull bp[4] = {pack2(b0.x, b0.y), pack2(b0.z, b0.w),
                             pack2(b1.x, b1.y), pack2(b1.z, b1.w)};
                float av[8] = {a0.x, a0.y, a0.z, a0.w, a1.x, a1.y, a1.z, a1.w};
                #pragma unroll
                for (int r = 0; r < 8; r++) {
                    ull ad = dup2(av[r]);
                    #pragma unroll
                    for (int cc = 0; cc < 4; cc++) acc[r][cc] = ffma2(ad, bp[cc], acc[r][cc]);
                }
            }
        }
    }

    __syncthreads();
    float* C1 = sb_;
    float* C2 = sb_ + 4352;
    if (!skip_gemm) {
        float* Cm = half ? C2 : C1;
        #pragma unroll
        for (int r = 0; r < 8; r++) {
            float o[8];
            #pragma unroll
            for (int cc = 0; cc < 4; cc++) {
                float2 f = unpk2(acc[r][cc]);
                o[2 * cc] = f.x * 0.125f; o[2 * cc + 1] = f.y * 0.125f;
            }
            float* pd = Cm + (l0 + r) * 68 + s0;
            *(float4*)pd       = make_float4(o[0], o[1], o[2], o[3]);
            *(float4*)(pd + 4) = make_float4(o[4], o[5], o[6], o[7]);
        }
    }
    __syncthreads();

    const float gg = fminf(fmaxf(__expf(*p0), 1e-3f), 20.0f);
    const float tg = fminf(fmaxf(__expf(*p1), 1e-3f), 10.0f);
    const float gd = fminf(fmaxf(__expf(*p2), 1e-3f), 20.0f);
    const float td = fminf(fmaxf(__expf(*p3), 1e-3f), 10.0f);
    const float itg = 1.0f / tg, itd = 1.0f / td, gdd = gd / td;

    // ---- Phase 2 (sign-split): 128 threads cover the 64x64 pair-tile.
    // Thread owns row r = tid>>1 of tile (i,j), col half (tid&1)*32.
    {
        const int r = tid >> 1;
        const int c0 = (tid & 1) << 5;
        const float* C2d = dg ? C1 : C2;
        float* arow = att + ((size_t)bh * LLEN + i * 64 + r) * LLEN + j * 64;
        #pragma unroll
        for (int s4 = c0; s4 < c0 + 32; s4 += 4) {
            float4 g1 = *(const float4*)(C1 + r * 68 + s4);
            float o[4];
            #pragma unroll
            for (int u = 0; u < 4; u++) {
                const int s = s4 + u;
                float g1v = (&g1.x)[u];
                float g2v = C2d[s * 68 + r];
                float Ss = 0.5f * (g1v + g2v);
                float Aa = 0.5f * (g1v - g2v);
                float t1 = tanha(Ss * itg);
                float s1 = fmaf(tanha(0.5f * gg * t1), 0.5f, 0.5f);  // sigmoid(gg*t1)
                float t2 = tanha(Aa * itd);
                float s2 = fmaf(tanha(0.5f * gd * t2), 0.5f, 0.5f);  // sigmoid(gd*t2)
                float t3 = tanha(Aa * gdd);
                float aij = fmaxf(t3, 0.0f) * s1 * s2;
                if (dg && s == r) aij = 0.0f;
                o[u] = aij;
                if (!dg) {
                    // att(j,i)[s,r]: A -> -A, sigma(-x) = 1-sigma(x).
                    float aji = fmaxf(-t3, 0.0f) * s1 * (1.0f - s2);
                    C2[s * 68 + r] = aji;   // in-place: slot read only by this thread
                }
            }
            *(float4*)(arow + s4) = make_float4(o[0], o[1], o[2], o[3]);
        }
    }
    __syncthreads();
    if (!dg) {
        // Flush att(j,i) tile: C2 now holds aji with row c contiguous in r.
        float* abase = att + ((size_t)bh * LLEN + j * 64) * LLEN + i * 64;
        #pragma unroll
        for (int t = tid; t < 1024; t += 128) {
            const int rr = t >> 4, q4 = (t & 15) << 2;
            *(float4*)(abase + (size_t)rr * LLEN + q4) = *(const float4*)(C2 + rr * 68 + q4);
        }
    }
}

// ============================================================================
// K3 (unchanged, proven): split-K att*V + entropy partials, NSPLIT=8.
// ============================================================================
__global__ __launch_bounds__(128, 4) void k3_av(const float* __restrict__ att,
                                                const float* __restrict__ val,
                                                float* __restrict__ pv,
                                                float* __restrict__ pe) {
    __shared__ float As[128][36];
    __shared__ float Vs[32][68];
    const int bh = blockIdx.y, b = bh >> 3, h = bh & 7;
    const int lb = blockIdx.x << 7;
    const int sp = blockIdx.z;
    const int tid = threadIdx.x;
    const int eg = tid & 7, lgp = tid >> 3;
    const int lrow0 = lgp << 3, e0 = eg << 3;

    ull acc[8][4];
    #pragma unroll
    for (int r = 0; r < 8; r++)
        #pragma unroll
        for (int c = 0; c < 4; c++) acc[r][c] = 0ull;
    float entacc = 0.0f;

    const float* attbase = att + ((size_t)bh * LLEN + lb) * LLEN;

    const int cb0 = sp << 2;
    for (int cb = cb0; cb < cb0 + 4; cb++) {
        const int sb = cb << 5;
        __syncthreads();
        #pragma unroll
        for (int t = tid; t < 1024; t += 128) {
            int rr = t >> 3, c4 = (t & 7) << 2;
            *(float4*)&As[rr][c4] = *(const float4*)(attbase + (size_t)rr * LLEN + sb + c4);
        }
        #pragma unroll
        for (int t = tid; t < 512; t += 128) {
            int rr = t >> 4, c4 = (t & 15) << 2;
            *(float4*)&Vs[rr][c4] = *(const float4*)(val + (((size_t)(b * LLEN + sb + rr)) * 8 + h) * 64 + c4);
        }
        __syncthreads();

        #pragma unroll
        for (int s4 = 0; s4 < 32; s4 += 4) {
            float4 a4[8];
            #pragma unroll
            for (int r = 0; r < 8; r++) a4[r] = *(const float4*)&As[lrow0 + r][s4];
            #pragma unroll
            for (int u = 0; u < 4; u++) {
                int ss = s4 + u;
                float4 w0 = *(const float4*)&Vs[ss][e0];
                float4 w1 = *(const float4*)&Vs[ss][e0 + 4];
                ull v2[4] = {pack2(w0.x, w0.y), pack2(w0.z, w0.w),
                             pack2(w1.x, w1.y), pack2(w1.z, w1.w)};
                #pragma unroll
                for (int r = 0; r < 8; r++) {
                    ull ad = dup2((&a4[r].x)[u]);
                    #pragma unroll
                    for (int c = 0; c < 4; c++) acc[r][c] = ffma2(ad, v2[c], acc[r][c]);
                }
            }
        }
        #pragma unroll
        for (int s4 = 0; s4 < 32; s4 += 4) {
            float4 a = *(const float4*)&As[tid][s4];
            entacc += a.x * __logf(fmaxf(a.x, 1e-8f));
            entacc += a.y * __logf(fmaxf(a.y, 1e-8f));
            entacc += a.z * __logf(fmaxf(a.z, 1e-8f));
            entacc += a.w * __logf(fmaxf(a.w, 1e-8f));
        }
    }

    pe[(size_t)sp * ENT_ELEMS_C + (size_t)bh * LLEN + lb + tid] = entacc;

    float* pvs = pv + (size_t)sp * V_ELEMS_C;
    #pragma unroll
    for (int r = 0; r < 8; r++) {
        int l = lb + lrow0 + r;
        float o[8];
        #pragma unroll
        for (int c = 0; c < 4; c++) {
            float2 f = unpk2(acc[r][c]);
            o[2 * c] = f.x; o[2 * c + 1] = f.y;
        }
        float* pd = pvs + (((size_t)(b * LLEN + l)) * 8 + h) * 64 + e0;
        *(float4*)pd       = make_float4(o[0], o[1], o[2], o[3]);
        *(float4*)(pd + 4) = make_float4(o[4], o[5], o[6], o[7]);
    }
}

// ============================================================================
// K4: deterministic split reduction, float4-vectorized V path.
// ============================================================================
#define V4_ELEMS (V_ELEMS_C / 4)
__global__ __launch_bounds__(256) void k4_reduce(const float4* __restrict__ pv4,
                                                 const float* __restrict__ pe,
                                                 float4* __restrict__ vout4,
                                                 float* __restrict__ ent) {
    int idx = blockIdx.x * 256 + threadIdx.x;
    if (idx < V4_ELEMS) {
        float4 s = pv4[idx];
        #pragma unroll
        for (int m = 1; m < NSPLIT; m++) {
            float4 t = pv4[idx + (size_t)m * V4_ELEMS];
            s.x += t.x; s.y += t.y; s.z += t.z; s.w += t.w;
        }
        vout4[idx] = s;
    } else {
        int e = idx - V4_ELEMS;
        if (e < ENT_ELEMS_C) {
            float s = pe[e];
            #pragma unroll
            for (int m = 1; m < NSPLIT; m++) s += pe[e + (size_t)m * ENT_ELEMS_C];
            ent[e] = -s;
        }
    }
}

// ============================================================================
// Launch: kA -> k3 -> k4. Graph-capturable, no alloc, no statics.
// ============================================================================
extern "C" void kernel_launch(void* const* d_in, const int* in_sizes, int n_in,
                              void* d_out, int out_size) {
    const float* q = (const float*)d_in[0];
    const float* k = (const float*)d_in[1];
    const float* v = (const float*)d_in[2];
    const float* lgg = (const float*)d_in[n_in - 4];
    const float* ltg = (const float*)d_in[n_in - 3];
    const float* lgd = (const float*)d_in[n_in - 2];
    const float* ltd = (const float*)d_in[n_in - 1];

    const long V_ELEMS   = V_ELEMS_C;
    const long ATT_ELEMS = (long)NBH * LLEN * LLEN;
    const long ENT_ELEMS = ENT_ELEMS_C;

    float* out = (float*)d_out;
    float* vptr = out;
    float* attp;
    float* entp;
    if ((long)out_size >= V_ELEMS + ATT_ELEMS + ENT_ELEMS) {
        attp = out + V_ELEMS;
        entp = out + V_ELEMS + ATT_ELEMS;
    } else {
        void* p1 = nullptr; void* p2 = nullptr;
        cudaGetSymbolAddress(&p1, g_att_fb);
        cudaGetSymbolAddress(&p2, g_ent_fb);
        attp = (float*)p1;
        entp = (float*)p2;
    }

    void* ppv = nullptr; void* ppe = nullptr;
    cudaGetSymbolAddress(&ppv, g_pv);
    cudaGetSymbolAddress(&ppe, g_pe);

    kA<<<dim3(136, 16), 128>>>(q, k, attp, lgg, ltg, lgd, ltd);
    k3_av<<<dim3(8, 16, NSPLIT), 128>>>(attp, v, (float*)ppv, (float*)ppe);
    k4_reduce<<<(V4_ELEMS + ENT_ELEMS_C + 255) / 256, 256>>>((const float4*)ppv, (const float*)ppe,
                                                             (float4*)vptr, entp);
}

// round 16
// speedup vs baseline: 1.9415x; 1.1078x over previous
#include <cuda_runtime.h>
#include <cstdint>

#define LLEN 1024
#define NBH 16
#define NSPLIT 8
#define V_ELEMS_C 1048576
#define ENT_ELEMS_C 16384

typedef unsigned long long ull;

// Fallbacks in case d_out only holds V (defensive vs. output-layout surprises).
__device__ float g_att_fb[(size_t)NBH * LLEN * LLEN];
__device__ float g_ent_fb[(size_t)NBH * LLEN];
// Split-K partials (deterministic two-pass reduction).
__device__ float g_pv[(size_t)NSPLIT * V_ELEMS_C];
__device__ float g_pe[(size_t)NSPLIT * ENT_ELEMS_C];

// ---- packed f32x2 helpers ----
__device__ __forceinline__ ull pack2(float lo, float hi) {
    ull r; asm("mov.b64 %0, {%1, %2};" : "=l"(r) : "f"(lo), "f"(hi)); return r;
}
__device__ __forceinline__ ull dup2(float x) {
    ull r; asm("mov.b64 %0, {%1, %1};" : "=l"(r) : "f"(x)); return r;
}
__device__ __forceinline__ ull ffma2(ull a, ull b, ull c) {
    ull d; asm("fma.rn.f32x2 %0, %1, %2, %3;" : "=l"(d) : "l"(a), "l"(b), "l"(c)); return d;
}
__device__ __forceinline__ float2 unpk2(ull v) {
    float2 f; asm("mov.b64 {%0, %1}, %2;" : "=f"(f.x), "=f"(f.y) : "l"(v)); return f;
}
__device__ __forceinline__ float tanha(float x) {
    float y; asm("tanh.approx.f32 %0, %1;" : "=f"(y) : "f"(x)); return y;
}

// ============================================================================
// Fused kernel A: pair-tile scores + elementwise att (R15 sign-split kept).
// R16: staging swizzle gains an r-bit5 term (rs ^= (r&32)>>3) so GEMM
// fragment reads at cols {x, x+32} land in distinct banks -> B-frag
// LDS conflicts eliminated.
// ============================================================================
__global__ __launch_bounds__(128, 4) void kA(const float* __restrict__ q,
                                             const float* __restrict__ kk,
                                             float* __restrict__ att,
                                             const float* __restrict__ p0,
                                             const float* __restrict__ p1,
                                             const float* __restrict__ p2,
                                             const float* __restrict__ p3) {
    __shared__ float sb_[8704];
    const int p = blockIdx.x, bh = blockIdx.y;
    const int b = bh >> 3, h = bh & 7;
    int i = (int)((__fsqrt_rn(8.0f * p + 1.0f) - 1.0f) * 0.5f);
    while ((i + 1) * (i + 2) / 2 <= p) i++;
    while (i * (i + 1) / 2 > p) i--;
    const int j = p - i * (i + 1) / 2;
    const bool dg = (i == j);

    const int tid = threadIdx.x;
    const int half = tid >> 6, t6 = tid & 63;
    const int l0 = (t6 >> 3) << 3, s0 = (t6 & 7) << 3;

    float* Qi = sb_;
    float* Kj = sb_ + 2176;
    float* Qj = sb_ + 4352;
    float* Ki = sb_ + 6528;
    const float* A_ = half ? Qj : Qi;
    const float* B_ = half ? Ki : Kj;

    const bool skip_gemm = (half && dg);   // diag: C2==C1, half-1 GEMM redundant

    ull acc[8][4];
    #pragma unroll
    for (int r = 0; r < 8; r++)
        #pragma unroll
        for (int c = 0; c < 4; c++) acc[r][c] = 0ull;

    const int xb = (l0 & 32) >> 3;   // reader-side bit5 XOR terms (const/thread)
    const int xs = (s0 & 32) >> 3;

    for (int c = 0; c < 2; c++) {
        __syncthreads();
        const int e0c = c << 5;
        #pragma unroll
        for (int t = tid; t < 2048; t += 128) {
            int tile = t >> 9, r = (t >> 3) & 63, e4 = (t & 7) << 2;
            int row; const float* src; float* dst;
            if (tile == 0)      { row = i * 64 + r; src = q;  dst = Qi; }
            else if (tile == 1) { row = j * 64 + r; src = kk; dst = Kj; }
            else if (tile == 2) { row = j * 64 + r; src = q;  dst = Qj; }
            else                { row = i * 64 + r; src = kk; dst = Ki; }
            float4 v = *(const float4*)(src + (((size_t)(b * LLEN + row)) * 8 + h) * 64 + e0c + e4);
            // conflict-free transposed STS incl. bit5 spread for frag reads
            const int rs = (r ^ e4) ^ ((r & 32) >> 3);
            dst[(e4 + 0) * 68 + rs] = v.x; dst[(e4 + 1) * 68 + rs] = v.y;
            dst[(e4 + 2) * 68 + rs] = v.z; dst[(e4 + 3) * 68 + rs] = v.w;
        }
        __syncthreads();
        if (!skip_gemm) {
            #pragma unroll 8
            for (int e = 0; e < 32; e++) {
                const int fe = e & 28;
                const float* Ae = A_ + e * 68;
                const float* Be = B_ + e * 68;
                float4 a0 = *(const float4*)(Ae + ((l0 ^ fe) ^ xb));
                float4 a1 = *(const float4*)(Ae + (((l0 + 4) ^ fe) ^ xb));
                float4 b0 = *(const float4*)(Be + ((s0 ^ fe) ^ xs));
                float4 b1 = *(const float4*)(Be + (((s0 + 4) ^ fe) ^ xs));
                ull bp[4] = {pack2(b0.x, b0.y), pack2(b0.z, b0.w),
                             pack2(b1.x, b1.y), pack2(b1.z, b1.w)};
                float av[8] = {a0.x, a0.y, a0.z, a0.w, a1.x, a1.y, a1.z, a1.w};
                #pragma unroll
                for (int r = 0; r < 8; r++) {
                    ull ad = dup2(av[r]);
                    #pragma unroll
                    for (int cc = 0; cc < 4; cc++) acc[r][cc] = ffma2(ad, bp[cc], acc[r][cc]);
                }
            }
        }
    }

    __syncthreads();
    float* C1 = sb_;
    float* C2 = sb_ + 4352;
    if (!skip_gemm) {
        float* Cm = half ? C2 : C1;
        #pragma unroll
        for (int r = 0; r < 8; r++) {
            float o[8];
            #pragma unroll
            for (int cc = 0; cc < 4; cc++) {
                float2 f = unpk2(acc[r][cc]);
                o[2 * cc] = f.x * 0.125f; o[2 * cc + 1] = f.y * 0.125f;
            }
            float* pd = Cm + (l0 + r) * 68 + s0;
            *(float4*)pd       = make_float4(o[0], o[1], o[2], o[3]);
            *(float4*)(pd + 4) = make_float4(o[4], o[5], o[6], o[7]);
        }
    }
    __syncthreads();

    const float gg = fminf(fmaxf(__expf(*p0), 1e-3f), 20.0f);
    const float tg = fminf(fmaxf(__expf(*p1), 1e-3f), 10.0f);
    const float gd = fminf(fmaxf(__expf(*p2), 1e-3f), 20.0f);
    const float td = fminf(fmaxf(__expf(*p3), 1e-3f), 10.0f);
    const float itg = 1.0f / tg, itd = 1.0f / td, gdd = gd / td;

    // ---- Phase 2 (sign-split, unchanged from R15) ----
    {
        const int r = tid >> 1;
        const int c0 = (tid & 1) << 5;
        const float* C2d = dg ? C1 : C2;
        float* arow = att + ((size_t)bh * LLEN + i * 64 + r) * LLEN + j * 64;
        #pragma unroll
        for (int s4 = c0; s4 < c0 + 32; s4 += 4) {
            float4 g1 = *(const float4*)(C1 + r * 68 + s4);
            float o[4];
            #pragma unroll
            for (int u = 0; u < 4; u++) {
                const int s = s4 + u;
                float g1v = (&g1.x)[u];
                float g2v = C2d[s * 68 + r];
                float Ss = 0.5f * (g1v + g2v);
                float Aa = 0.5f * (g1v - g2v);
                float t1 = tanha(Ss * itg);
                float s1 = fmaf(tanha(0.5f * gg * t1), 0.5f, 0.5f);
                float t2 = tanha(Aa * itd);
                float s2 = fmaf(tanha(0.5f * gd * t2), 0.5f, 0.5f);
                float t3 = tanha(Aa * gdd);
                float aij = fmaxf(t3, 0.0f) * s1 * s2;
                if (dg && s == r) aij = 0.0f;
                o[u] = aij;
                if (!dg) {
                    float aji = fmaxf(-t3, 0.0f) * s1 * (1.0f - s2);
                    C2[s * 68 + r] = aji;   // in-place: slot read only by this thread
                }
            }
            *(float4*)(arow + s4) = make_float4(o[0], o[1], o[2], o[3]);
        }
    }
    __syncthreads();
    if (!dg) {
        float* abase = att + ((size_t)bh * LLEN + j * 64) * LLEN + i * 64;
        #pragma unroll
        for (int t = tid; t < 1024; t += 128) {
            const int rr = t >> 4, q4 = (t & 15) << 2;
            *(float4*)(abase + (size_t)rr * LLEN + q4) = *(const float4*)(C2 + rr * 68 + q4);
        }
    }
}

// ============================================================================
// K3: split-K att*V + entropy. R16: XOR bank swizzles.
//  As col' = c ^ 8*((row>>3)&3): a4 frag reads were 4-way (36*8 % 32 == 0),
//    now conflict-free; readers use constant-per-thread XOR (lgp&3)<<3.
//  Vs col' = c ^ ((c>>3)&4): V-frag reads were 2-way (e0, e0+32 same bank),
//    now 8 distinct bank-quads.
// ============================================================================
__global__ __launch_bounds__(128, 4) void k3_av(const float* __restrict__ att,
                                                const float* __restrict__ val,
                                                float* __restrict__ pv,
                                                float* __restrict__ pe) {
    __shared__ float As[128][36];
    __shared__ float Vs[32][68];
    const int bh = blockIdx.y, b = bh >> 3, h = bh & 7;
    const int lb = blockIdx.x << 7;
    const int sp = blockIdx.z;
    const int tid = threadIdx.x;
    const int eg = tid & 7, lgp = tid >> 3;
    const int lrow0 = lgp << 3, e0 = eg << 3;

    const int axr = (lgp & 3) << 3;        // As reader XOR (const per thread)
    const int axe = ((tid >> 3) & 3) << 3; // As entropy-row XOR
    const int vx  = eg & 4;                // Vs reader XOR

    ull acc[8][4];
    #pragma unroll
    for (int r = 0; r < 8; r++)
        #pragma unroll
        for (int c = 0; c < 4; c++) acc[r][c] = 0ull;
    float entacc = 0.0f;

    const float* attbase = att + ((size_t)bh * LLEN + lb) * LLEN;

    const int cb0 = sp << 2;
    for (int cb = cb0; cb < cb0 + 4; cb++) {
        const int sb = cb << 5;
        __syncthreads();
        #pragma unroll
        for (int t = tid; t < 1024; t += 128) {
            int rr = t >> 3, c4 = (t & 7) << 2;
            *(float4*)&As[rr][c4 ^ (((rr >> 3) & 3) << 3)] =
                *(const float4*)(attbase + (size_t)rr * LLEN + sb + c4);
        }
        #pragma unroll
        for (int t = tid; t < 512; t += 128) {
            int rr = t >> 4, c4 = (t & 15) << 2;
            *(float4*)&Vs[rr][c4 ^ ((c4 >> 3) & 4)] =
                *(const float4*)(val + (((size_t)(b * LLEN + sb + rr)) * 8 + h) * 64 + c4);
        }
        __syncthreads();

        #pragma unroll
        for (int s4 = 0; s4 < 32; s4 += 4) {
            float4 a4[8];
            #pragma unroll
            for (int r = 0; r < 8; r++) a4[r] = *(const float4*)&As[lrow0 + r][s4 ^ axr];
            #pragma unroll
            for (int u = 0; u < 4; u++) {
                int ss = s4 + u;
                float4 w0 = *(const float4*)&Vs[ss][e0 ^ vx];
                float4 w1 = *(const float4*)&Vs[ss][(e0 + 4) ^ vx];
                ull v2[4] = {pack2(w0.x, w0.y), pack2(w0.z, w0.w),
                             pack2(w1.x, w1.y), pack2(w1.z, w1.w)};
                #pragma unroll
                for (int r = 0; r < 8; r++) {
                    ull ad = dup2((&a4[r].x)[u]);
                    #pragma unroll
                    for (int c = 0; c < 4; c++) acc[r][c] = ffma2(ad, v2[c], acc[r][c]);
                }
            }
        }
        #pragma unroll
        for (int s4 = 0; s4 < 32; s4 += 4) {
            float4 a = *(const float4*)&As[tid][s4 ^ axe];
            entacc += a.x * __logf(fmaxf(a.x, 1e-8f));
            entacc += a.y * __logf(fmaxf(a.y, 1e-8f));
            entacc += a.z * __logf(fmaxf(a.z, 1e-8f));
            entacc += a.w * __logf(fmaxf(a.w, 1e-8f));
        }
    }

    pe[(size_t)sp * ENT_ELEMS_C + (size_t)bh * LLEN + lb + tid] = entacc;

    float* pvs = pv + (size_t)sp * V_ELEMS_C;
    #pragma unroll
    for (int r = 0; r < 8; r++) {
        int l = lb + lrow0 + r;
        float o[8];
        #pragma unroll
        for (int c = 0; c < 4; c++) {
            float2 f = unpk2(acc[r][c]);
            o[2 * c] = f.x; o[2 * c + 1] = f.y;
        }
        float* pd = pvs + (((size_t)(b * LLEN + l)) * 8 + h) * 64 + e0;
        *(float4*)pd       = make_float4(o[0], o[1], o[2], o[3]);
        *(float4*)(pd + 4) = make_float4(o[4], o[5], o[6], o[7]);
    }
}

// ============================================================================
// K4: deterministic split reduction, float4-vectorized V path.
// ============================================================================
#define V4_ELEMS (V_ELEMS_C / 4)
__global__ __launch_bounds__(256) void k4_reduce(const float4* __restrict__ pv4,
                                                 const float* __restrict__ pe,
                                                 float4* __restrict__ vout4,
                                                 float* __restrict__ ent) {
    int idx = blockIdx.x * 256 + threadIdx.x;
    if (idx < V4_ELEMS) {
        float4 s = pv4[idx];
        #pragma unroll
        for (int m = 1; m < NSPLIT; m++) {
            float4 t = pv4[idx + (size_t)m * V4_ELEMS];
            s.x += t.x; s.y += t.y; s.z += t.z; s.w += t.w;
        }
        vout4[idx] = s;
    } else {
        int e = idx - V4_ELEMS;
        if (e < ENT_ELEMS_C) {
            float s = pe[e];
            #pragma unroll
            for (int m = 1; m < NSPLIT; m++) s += pe[e + (size_t)m * ENT_ELEMS_C];
            ent[e] = -s;
        }
    }
}

// ============================================================================
// Launch: kA -> k3 -> k4. Graph-capturable, no alloc, no statics.
// ============================================================================
extern "C" void kernel_launch(void* const* d_in, const int* in_sizes, int n_in,
                              void* d_out, int out_size) {
    const float* q = (const float*)d_in[0];
    const float* k = (const float*)d_in[1];
    const float* v = (const float*)d_in[2];
    const float* lgg = (const float*)d_in[n_in - 4];
    const float* ltg = (const float*)d_in[n_in - 3];
    const float* lgd = (const float*)d_in[n_in - 2];
    const float* ltd = (const float*)d_in[n_in - 1];

    const long V_ELEMS   = V_ELEMS_C;
    const long ATT_ELEMS = (long)NBH * LLEN * LLEN;
    const long ENT_ELEMS = ENT_ELEMS_C;

    float* out = (float*)d_out;
    float* vptr = out;
    float* attp;
    float* entp;
    if ((long)out_size >= V_ELEMS + ATT_ELEMS + ENT_ELEMS) {
        attp = out + V_ELEMS;
        entp = out + V_ELEMS + ATT_ELEMS;
    } else {
        void* p1 = nullptr; void* p2 = nullptr;
        cudaGetSymbolAddress(&p1, g_att_fb);
        cudaGetSymbolAddress(&p2, g_ent_fb);
        attp = (float*)p1;
        entp = (float*)p2;
    }

    void* ppv = nullptr; void* ppe = nullptr;
    cudaGetSymbolAddress(&ppv, g_pv);
    cudaGetSymbolAddress(&ppe, g_pe);

    kA<<<dim3(136, 16), 128>>>(q, k, attp, lgg, ltg, lgd, ltd);
    k3_av<<<dim3(8, 16, NSPLIT), 128>>>(attp, v, (float*)ppv, (float*)ppe);
    k4_reduce<<<(V4_ELEMS + ENT_ELEMS_C + 255) / 256, 256>>>((const float4*)ppv, (const float*)ppe,
                                                             (float4*)vptr, entp);
}

// round 17
// speedup vs baseline: 1.9679x; 1.0136x over previous
#include <cuda_runtime.h>
#include <cstdint>

#define LLEN 1024
#define NBH 16
#define NSPLIT 8
#define V_ELEMS_C 1048576
#define ENT_ELEMS_C 16384

typedef unsigned long long ull;

// Fallbacks in case d_out only holds V (defensive vs. output-layout surprises).
__device__ float g_att_fb[(size_t)NBH * LLEN * LLEN];
__device__ float g_ent_fb[(size_t)NBH * LLEN];
// Split-K partials (deterministic two-pass reduction).
__device__ float g_pv[(size_t)NSPLIT * V_ELEMS_C];
__device__ float g_pe[(size_t)NSPLIT * ENT_ELEMS_C];

// ---- packed f32x2 helpers ----
__device__ __forceinline__ ull pack2(float lo, float hi) {
    ull r; asm("mov.b64 %0, {%1, %2};" : "=l"(r) : "f"(lo), "f"(hi)); return r;
}
__device__ __forceinline__ ull dup2(float x) {
    ull r; asm("mov.b64 %0, {%1, %1};" : "=l"(r) : "f"(x)); return r;
}
__device__ __forceinline__ ull ffma2(ull a, ull b, ull c) {
    ull d; asm("fma.rn.f32x2 %0, %1, %2, %3;" : "=l"(d) : "l"(a), "l"(b), "l"(c)); return d;
}
__device__ __forceinline__ float2 unpk2(ull v) {
    float2 f; asm("mov.b64 {%0, %1}, %2;" : "=f"(f.x), "=f"(f.y) : "l"(v)); return f;
}
__device__ __forceinline__ float tanha(float x) {
    float y; asm("tanh.approx.f32 %0, %1;" : "=f"(y) : "f"(x)); return y;
}
__device__ __forceinline__ uint32_t smem_u32(const void* p) {
    uint32_t a;
    asm("{ .reg .u64 t; cvta.to.shared.u64 t, %1; cvt.u32.u64 %0, t; }" : "=r"(a) : "l"(p));
    return a;
}
// cp.async (LDGSTS): Ampere+ plain PTX (no sm_103a-only features).
#define CPA16(dst_u32, src_ptr) \
    asm volatile("cp.async.cg.shared.global [%0], [%1], 16;" :: "r"(dst_u32), "l"(src_ptr))
#define CPA_COMMIT() asm volatile("cp.async.commit_group;" ::: "memory")
#define CPA_WAIT1()  asm volatile("cp.async.wait_group 1;" ::: "memory")
#define CPA_WAIT0()  asm volatile("cp.async.wait_group 0;" ::: "memory")

// ============================================================================
// Fused kernel A (unchanged from R16 -- at its issue-port ceiling).
// ============================================================================
__global__ __launch_bounds__(128, 4) void kA(const float* __restrict__ q,
                                             const float* __restrict__ kk,
                                             float* __restrict__ att,
                                             const float* __restrict__ p0,
                                             const float* __restrict__ p1,
                                             const float* __restrict__ p2,
                                             const float* __restrict__ p3) {
    __shared__ float sb_[8704];
    const int p = blockIdx.x, bh = blockIdx.y;
    const int b = bh >> 3, h = bh & 7;
    int i = (int)((__fsqrt_rn(8.0f * p + 1.0f) - 1.0f) * 0.5f);
    while ((i + 1) * (i + 2) / 2 <= p) i++;
    while (i * (i + 1) / 2 > p) i--;
    const int j = p - i * (i + 1) / 2;
    const bool dg = (i == j);

    const int tid = threadIdx.x;
    const int half = tid >> 6, t6 = tid & 63;
    const int l0 = (t6 >> 3) << 3, s0 = (t6 & 7) << 3;

    float* Qi = sb_;
    float* Kj = sb_ + 2176;
    float* Qj = sb_ + 4352;
    float* Ki = sb_ + 6528;
    const float* A_ = half ? Qj : Qi;
    const float* B_ = half ? Ki : Kj;

    const bool skip_gemm = (half && dg);

    ull acc[8][4];
    #pragma unroll
    for (int r = 0; r < 8; r++)
        #pragma unroll
        for (int c = 0; c < 4; c++) acc[r][c] = 0ull;

    const int xb = (l0 & 32) >> 3;
    const int xs = (s0 & 32) >> 3;

    for (int c = 0; c < 2; c++) {
        __syncthreads();
        const int e0c = c << 5;
        #pragma unroll
        for (int t = tid; t < 2048; t += 128) {
            int tile = t >> 9, r = (t >> 3) & 63, e4 = (t & 7) << 2;
            int row; const float* src; float* dst;
            if (tile == 0)      { row = i * 64 + r; src = q;  dst = Qi; }
            else if (tile == 1) { row = j * 64 + r; src = kk; dst = Kj; }
            else if (tile == 2) { row = j * 64 + r; src = q;  dst = Qj; }
            else                { row = i * 64 + r; src = kk; dst = Ki; }
            float4 v = *(const float4*)(src + (((size_t)(b * LLEN + row)) * 8 + h) * 64 + e0c + e4);
            const int rs = (r ^ e4) ^ ((r & 32) >> 3);
            dst[(e4 + 0) * 68 + rs] = v.x; dst[(e4 + 1) * 68 + rs] = v.y;
            dst[(e4 + 2) * 68 + rs] = v.z; dst[(e4 + 3) * 68 + rs] = v.w;
        }
        __syncthreads();
        if (!skip_gemm) {
            #pragma unroll 8
            for (int e = 0; e < 32; e++) {
                const int fe = e & 28;
                const float* Ae = A_ + e * 68;
                const float* Be = B_ + e * 68;
                float4 a0 = *(const float4*)(Ae + ((l0 ^ fe) ^ xb));
                float4 a1 = *(const float4*)(Ae + (((l0 + 4) ^ fe) ^ xb));
                float4 b0 = *(const float4*)(Be + ((s0 ^ fe) ^ xs));
                float4 b1 = *(const float4*)(Be + (((s0 + 4) ^ fe) ^ xs));
                ull bp[4] = {pack2(b0.x, b0.y), pack2(b0.z, b0.w),
                             pack2(b1.x, b1.y), pack2(b1.z, b1.w)};
                float av[8] = {a0.x, a0.y, a0.z, a0.w, a1.x, a1.y, a1.z, a1.w};
                #pragma unroll
                for (int r = 0; r < 8; r++) {
                    ull ad = dup2(av[r]);
                    #pragma unroll
                    for (int cc = 0; cc < 4; cc++) acc[r][cc] = ffma2(ad, bp[cc], acc[r][cc]);
                }
            }
        }
    }

    __syncthreads();
    float* C1 = sb_;
    float* C2 = sb_ + 4352;
    if (!skip_gemm) {
        float* Cm = half ? C2 : C1;
        #pragma unroll
        for (int r = 0; r < 8; r++) {
            float o[8];
            #pragma unroll
            for (int cc = 0; cc < 4; cc++) {
                float2 f = unpk2(acc[r][cc]);
                o[2 * cc] = f.x * 0.125f; o[2 * cc + 1] = f.y * 0.125f;
            }
            float* pd = Cm + (l0 + r) * 68 + s0;
            *(float4*)pd       = make_float4(o[0], o[1], o[2], o[3]);
            *(float4*)(pd + 4) = make_float4(o[4], o[5], o[6], o[7]);
        }
    }
    __syncthreads();

    const float gg = fminf(fmaxf(__expf(*p0), 1e-3f), 20.0f);
    const float tg = fminf(fmaxf(__expf(*p1), 1e-3f), 10.0f);
    const float gd = fminf(fmaxf(__expf(*p2), 1e-3f), 20.0f);
    const float td = fminf(fmaxf(__expf(*p3), 1e-3f), 10.0f);
    const float itg = 1.0f / tg, itd = 1.0f / td, gdd = gd / td;

    {
        const int r = tid >> 1;
        const int c0 = (tid & 1) << 5;
        const float* C2d = dg ? C1 : C2;
        float* arow = att + ((size_t)bh * LLEN + i * 64 + r) * LLEN + j * 64;
        #pragma unroll
        for (int s4 = c0; s4 < c0 + 32; s4 += 4) {
            float4 g1 = *(const float4*)(C1 + r * 68 + s4);
            float o[4];
            #pragma unroll
            for (int u = 0; u < 4; u++) {
                const int s = s4 + u;
                float g1v = (&g1.x)[u];
                float g2v = C2d[s * 68 + r];
                float Ss = 0.5f * (g1v + g2v);
                float Aa = 0.5f * (g1v - g2v);
                float t1 = tanha(Ss * itg);
                float s1 = fmaf(tanha(0.5f * gg * t1), 0.5f, 0.5f);
                float t2 = tanha(Aa * itd);
                float s2 = fmaf(tanha(0.5f * gd * t2), 0.5f, 0.5f);
                float t3 = tanha(Aa * gdd);
                float aij = fmaxf(t3, 0.0f) * s1 * s2;
                if (dg && s == r) aij = 0.0f;
                o[u] = aij;
                if (!dg) {
                    float aji = fmaxf(-t3, 0.0f) * s1 * (1.0f - s2);
                    C2[s * 68 + r] = aji;
                }
            }
            *(float4*)(arow + s4) = make_float4(o[0], o[1], o[2], o[3]);
        }
    }
    __syncthreads();
    if (!dg) {
        float* abase = att + ((size_t)bh * LLEN + j * 64) * LLEN + i * 64;
        #pragma unroll
        for (int t = tid; t < 1024; t += 128) {
            const int rr = t >> 4, q4 = (t & 15) << 2;
            *(float4*)(abase + (size_t)rr * LLEN + q4) = *(const float4*)(C2 + rr * 68 + q4);
        }
    }
}

// ============================================================================
// K3 R17: cp.async double-buffered pipeline over the 4 s-chunks.
// Dynamic smem: As[2][128][36] + Vs[2][32][68] = 54272 B (4 blocks/SM OK).
// Chunk c+1's LDGSTS overlap chunk c's FFMA2 compute; bank swizzles kept.
// ============================================================================
#define AS_STRIDE (128 * 36)
#define VS_STRIDE (32 * 68)
#define SMEM_K3 ((2 * AS_STRIDE + 2 * VS_STRIDE) * 4)

__global__ __launch_bounds__(128, 4) void k3_av(const float* __restrict__ att,
                                                const float* __restrict__ val,
                                                float* __restrict__ pv,
                                                float* __restrict__ pe) {
    extern __shared__ float dsm[];
    float* AsB = dsm;                    // 2 x [128][36]
    float* VsB = dsm + 2 * AS_STRIDE;    // 2 x [32][68]

    const int bh = blockIdx.y, b = bh >> 3, h = bh & 7;
    const int lb = blockIdx.x << 7;
    const int sp = blockIdx.z;
    const int tid = threadIdx.x;
    const int eg = tid & 7, lgp = tid >> 3;
    const int lrow0 = lgp << 3, e0 = eg << 3;

    const int axr = (lgp & 3) << 3;        // As reader XOR
    const int axe = ((tid >> 3) & 3) << 3; // entropy-row XOR
    const int vx  = eg & 4;                // Vs reader XOR

    ull acc[8][4];
    #pragma unroll
    for (int r = 0; r < 8; r++)
        #pragma unroll
        for (int c = 0; c < 4; c++) acc[r][c] = 0ull;
    float entacc = 0.0f;

    const float* attbase = att + ((size_t)bh * LLEN + lb) * LLEN;
    const int cb0 = sp << 2;

    // per-thread fixed slices for async staging (8 As float4 + 4 Vs float4)
    // As: t in [0,1024): rr = t>>3, c4 = (t&7)<<2 ; store col c4 ^ swz(rr)
    // Vs: t in [0,512):  rr = t>>4, c4 = (t&15)<<2; store col c4 ^ ((c4>>3)&4)
    auto stage = [&](int cb, int buf) {
        const int sb = cb << 5;
        float* As = AsB + buf * AS_STRIDE;
        float* Vs = VsB + buf * VS_STRIDE;
        #pragma unroll
        for (int t = tid; t < 1024; t += 128) {
            const int rr = t >> 3, c4 = (t & 7) << 2;
            const int cs = c4 ^ (((rr >> 3) & 3) << 3);
            CPA16(smem_u32(As + rr * 36 + cs),
                  attbase + (size_t)rr * LLEN + sb + c4);
        }
        #pragma unroll
        for (int t = tid; t < 512; t += 128) {
            const int rr = t >> 4, c4 = (t & 15) << 2;
            const int cs = c4 ^ ((c4 >> 3) & 4);
            CPA16(smem_u32(Vs + rr * 68 + cs),
                  val + (((size_t)(b * LLEN + sb + rr)) * 8 + h) * 64 + c4);
        }
        CPA_COMMIT();
    };

    stage(cb0, 0);

    for (int cc = 0; cc < 4; cc++) {
        const int cur = cc & 1;
        if (cc < 3) stage(cb0 + cc + 1, cur ^ 1);
        if (cc < 3) { CPA_WAIT1(); } else { CPA_WAIT0(); }
        __syncthreads();

        const float* As = AsB + cur * AS_STRIDE;
        const float* Vs = VsB + cur * VS_STRIDE;

        #pragma unroll
        for (int s4 = 0; s4 < 32; s4 += 4) {
            float4 a4[8];
            #pragma unroll
            for (int r = 0; r < 8; r++)
                a4[r] = *(const float4*)(As + (lrow0 + r) * 36 + (s4 ^ axr));
            #pragma unroll
            for (int u = 0; u < 4; u++) {
                int ss = s4 + u;
                float4 w0 = *(const float4*)(Vs + ss * 68 + (e0 ^ vx));
                float4 w1 = *(const float4*)(Vs + ss * 68 + ((e0 + 4) ^ vx));
                ull v2[4] = {pack2(w0.x, w0.y), pack2(w0.z, w0.w),
                             pack2(w1.x, w1.y), pack2(w1.z, w1.w)};
                #pragma unroll
                for (int r = 0; r < 8; r++) {
                    ull ad = dup2((&a4[r].x)[u]);
                    #pragma unroll
                    for (int c = 0; c < 4; c++) acc[r][c] = ffma2(ad, v2[c], acc[r][c]);
                }
            }
        }
        #pragma unroll
        for (int s4 = 0; s4 < 32; s4 += 4) {
            float4 a = *(const float4*)(As + tid * 36 + (s4 ^ axe));
            entacc += a.x * __logf(fmaxf(a.x, 1e-8f));
            entacc += a.y * __logf(fmaxf(a.y, 1e-8f));
            entacc += a.z * __logf(fmaxf(a.z, 1e-8f));
            entacc += a.w * __logf(fmaxf(a.w, 1e-8f));
        }
        __syncthreads();   // buf cur is reused by the prefetch two iterations out
    }

    pe[(size_t)sp * ENT_ELEMS_C + (size_t)bh * LLEN + lb + tid] = entacc;

    float* pvs = pv + (size_t)sp * V_ELEMS_C;
    #pragma unroll
    for (int r = 0; r < 8; r++) {
        int l = lb + lrow0 + r;
        float o[8];
        #pragma unroll
        for (int c = 0; c < 4; c++) {
            float2 f = unpk2(acc[r][c]);
            o[2 * c] = f.x; o[2 * c + 1] = f.y;
        }
        float* pd = pvs + (((size_t)(b * LLEN + l)) * 8 + h) * 64 + e0;
        *(float4*)pd       = make_float4(o[0], o[1], o[2], o[3]);
        *(float4*)(pd + 4) = make_float4(o[4], o[5], o[6], o[7]);
    }
}

// ============================================================================
// K4: deterministic split reduction, float4-vectorized V path.
// ============================================================================
#define V4_ELEMS (V_ELEMS_C / 4)
__global__ __launch_bounds__(256) void k4_reduce(const float4* __restrict__ pv4,
                                                 const float* __restrict__ pe,
                                                 float4* __restrict__ vout4,
                                                 float* __restrict__ ent) {
    int idx = blockIdx.x * 256 + threadIdx.x;
    if (idx < V4_ELEMS) {
        float4 s = pv4[idx];
        #pragma unroll
        for (int m = 1; m < NSPLIT; m++) {
            float4 t = pv4[idx + (size_t)m * V4_ELEMS];
            s.x += t.x; s.y += t.y; s.z += t.z; s.w += t.w;
        }
        vout4[idx] = s;
    } else {
        int e = idx - V4_ELEMS;
        if (e < ENT_ELEMS_C) {
            float s = pe[e];
            #pragma unroll
            for (int m = 1; m < NSPLIT; m++) s += pe[e + (size_t)m * ENT_ELEMS_C];
            ent[e] = -s;
        }
    }
}

// ============================================================================
// Launch: kA -> k3 -> k4. Graph-capturable, no alloc, no statics.
// ============================================================================
extern "C" void kernel_launch(void* const* d_in, const int* in_sizes, int n_in,
                              void* d_out, int out_size) {
    const float* q = (const float*)d_in[0];
    const float* k = (const float*)d_in[1];
    const float* v = (const float*)d_in[2];
    const float* lgg = (const float*)d_in[n_in - 4];
    const float* ltg = (const float*)d_in[n_in - 3];
    const float* lgd = (const float*)d_in[n_in - 2];
    const float* ltd = (const float*)d_in[n_in - 1];

    const long V_ELEMS   = V_ELEMS_C;
    const long ATT_ELEMS = (long)NBH * LLEN * LLEN;
    const long ENT_ELEMS = ENT_ELEMS_C;

    float* out = (float*)d_out;
    float* vptr = out;
    float* attp;
    float* entp;
    if ((long)out_size >= V_ELEMS + ATT_ELEMS + ENT_ELEMS) {
        attp = out + V_ELEMS;
        entp = out + V_ELEMS + ATT_ELEMS;
    } else {
        void* p1 = nullptr; void* p2 = nullptr;
        cudaGetSymbolAddress(&p1, g_att_fb);
        cudaGetSymbolAddress(&p2, g_ent_fb);
        attp = (float*)p1;
        entp = (float*)p2;
    }

    void* ppv = nullptr; void* ppe = nullptr;
    cudaGetSymbolAddress(&ppv, g_pv);
    cudaGetSymbolAddress(&ppe, g_pe);

    // Unconditional, idempotent (no static guards): opt k3 into >48KB dyn smem.
    cudaFuncSetAttribute(k3_av, cudaFuncAttributeMaxDynamicSharedMemorySize, SMEM_K3);

    kA<<<dim3(136, 16), 128>>>(q, k, attp, lgg, ltg, lgd, ltd);
    k3_av<<<dim3(8, 16, NSPLIT), 128, SMEM_K3>>>(attp, v, (float*)ppv, (float*)ppe);
    k4_reduce<<<(V4_ELEMS + ENT_ELEMS_C + 255) / 256, 256>>>((const float4*)ppv, (const float*)ppe,
                                                             (float4*)vptr, entp);
}